// round 11
// baseline (speedup 1.0000x reference)
#include <cuda_runtime.h>
#include <cuda_fp16.h>

#define BB 32
#define TT 1000
#define EE 512
#define DD 1024
#define AA 512
#define CC 10
#define FF 100
#define KW 201
#define ODIM_ 5000
#define LL 100
#define OLEN 101
#define SOS_ 4998
#define NROW 4096
#define KCAT2 1536
#define MOUT 3232
#define MOUT_PAD 3328
#define TCH 24
#define NTC 42    // ceil(1000/24)

__device__ __half g_preh[BB * TT * AA];          // 32.8 MB
__device__ __half g_hpadh[BB * TT * EE];         // 32.8 MB
__device__ __half g_wcat2h[NROW * KCAT2];        // 12.6 MB
__device__ float g_gey[MOUT_PAD * NROW];         // 54.5 MB (streamed)
__device__ __half2 g_wattp[10 * 256];
__device__ float g_aw[BB * TT];
__device__ float g_e[BB * TT];                   // exp(2e)
__device__ float g_epart[BB * NTC];
__device__ float g_decp[4][BB * AA];
__device__ float g_ctxp2[2][BB * EE];
__device__ float g_z[2][BB * DD];
__device__ float g_c[BB * DD];
__device__ float g_zall[MOUT_PAD * DD];

__device__ __forceinline__ __half2 tanh2(__half2 x) {
    unsigned xi = *reinterpret_cast<unsigned*>(&x), yi;
    asm("tanh.approx.f16x2 %0, %1;" : "=r"(yi) : "r"(xi));
    return *reinterpret_cast<__half2*>(&yi);
}

// ---------- pre-loop kernel 1 ----------
__global__ void k_prep(const float* __restrict__ w_ih, const float* __restrict__ w_hh,
                       const float* __restrict__ hpad, const float* __restrict__ w_att) {
    const size_t TOT = 22742784;
    for (size_t i = (size_t)blockIdx.x * 256 + threadIdx.x; i < TOT; i += 2097152) {
        if (i < 32768) {
            g_z[0][i] = 0.f; g_c[i] = 0.f;
        } else if (i < 64768) {
            g_aw[i - 32768] = 1.0f / TT;
        } else if (i < 6356224) {
            int j = (int)(i - 64768);
            int r = j / KCAT2, k = j - r * KCAT2;
            int n = (r & 3) * DD + (r >> 2);
            float v = (k < EE) ? w_ih[(size_t)n * (DD + EE) + DD + k]
                               : w_hh[(size_t)n * DD + (k - EE)];
            g_wcat2h[j] = __float2half(v);
        } else if (i < 22740224) {
            size_t j = i - 6356224;
            g_hpadh[j] = __float2half(hpad[j]);
        } else {
            int j = (int)(i - 22740224);
            int c = j >> 8, p = j & 255;
            g_wattp[j] = __floats2half2_rn(w_att[(2 * p) * CC + c],
                                           w_att[(2 * p + 1) * CC + c]);
        }
    }
}

// ---------- pre-loop kernel 2: fused one-time GEMMs ----------
__global__ __launch_bounds__(256) void k_gemms(const float* __restrict__ hpad,
                                               const float* __restrict__ w_enc,
                                               const float* __restrict__ b_enc,
                                               const float* __restrict__ w_ih,
                                               const float* __restrict__ b_ih,
                                               const float* __restrict__ b_hh,
                                               const int* __restrict__ ys,
                                               const float* __restrict__ embed) {
    __shared__ float As[16][132];
    __shared__ float Bs[16][132];
    __shared__ int tok_s[128];
    int tid = threadIdx.x;
    bool is_pre = blockIdx.x >= 832;
    int m0, n0, K;
    if (is_pre) {
        int idx = blockIdx.x - 832;
        m0 = (idx >> 2) * 128; n0 = (idx & 3) * 128; K = 512;
    } else {
        m0 = ((int)blockIdx.x >> 5) * 128; n0 = ((int)blockIdx.x & 31) * 128; K = 1024;
        if (tid < 128) {
            int m = m0 + tid;
            int s = m >> 5, b = m & 31;
            tok_s[tid] = (s == 0 || s > 100) ? SOS_ : ys[b * LL + s - 1];
        }
        __syncthreads();
    }
    float acc[8][8];
#pragma unroll
    for (int i = 0; i < 8; i++)
#pragma unroll
        for (int j = 0; j < 8; j++) acc[i][j] = 0.f;
    int tm0 = (tid >> 4) << 3, tn0 = (tid & 15) << 3;
    for (int k0 = 0; k0 < K; k0 += 16) {
#pragma unroll
        for (int i = 0; i < 2; i++) {
            int lin = tid + (i << 8);
            int row = lin >> 2, kq = (lin & 3) << 2;
            float4 va, vb;
            if (is_pre) {
                va = *(const float4*)(hpad + (size_t)(m0 + row) * 512 + k0 + kq);
                vb = *(const float4*)(w_enc + (size_t)(n0 + row) * 512 + k0 + kq);
            } else {
                va = *(const float4*)(embed + (size_t)tok_s[row] * DD + k0 + kq);
                int r = n0 + row;
                int orig = (r & 3) * DD + (r >> 2);
                vb = *(const float4*)(w_ih + (size_t)orig * (DD + EE) + k0 + kq);
            }
            As[kq + 0][row] = va.x; As[kq + 1][row] = va.y;
            As[kq + 2][row] = va.z; As[kq + 3][row] = va.w;
            Bs[kq + 0][row] = vb.x; Bs[kq + 1][row] = vb.y;
            Bs[kq + 2][row] = vb.z; Bs[kq + 3][row] = vb.w;
        }
        __syncthreads();
#pragma unroll
        for (int kk = 0; kk < 16; kk++) {
            float a[8], b[8];
            *(float4*)&a[0] = *(const float4*)&As[kk][tm0];
            *(float4*)&a[4] = *(const float4*)&As[kk][tm0 + 4];
            *(float4*)&b[0] = *(const float4*)&Bs[kk][tn0];
            *(float4*)&b[4] = *(const float4*)&Bs[kk][tn0 + 4];
#pragma unroll
            for (int i = 0; i < 8; i++)
#pragma unroll
                for (int j = 0; j < 8; j++)
                    acc[i][j] = fmaf(a[i], b[j], acc[i][j]);
        }
        __syncthreads();
    }
#pragma unroll
    for (int i = 0; i < 8; i++) {
        int m_ = m0 + tm0 + i;
#pragma unroll
        for (int j = 0; j < 8; j++) {
            int n_ = n0 + tn0 + j;
            if (is_pre) {
                g_preh[(size_t)m_ * 512 + n_] = __float2half(acc[i][j] + b_enc[n_]);
            } else {
                int orig = (n_ & 3) * DD + (n_ >> 2);
                __stcs(&g_gey[(size_t)m_ * NROW + n_], acc[i][j] + b_ih[orig] + b_hh[orig]);
            }
        }
    }
}

// ---------- per-step: dec GEMM K-split (64 blocks) ----------
__global__ __launch_bounds__(256) void k_dec(const float* __restrict__ w_dec, int step) {
    __shared__ float ws2[32][68];
    __shared__ float zs[64][36];
    int tid = threadIdx.x;
    int ks = blockIdx.x & 3, at = blockIdx.x >> 2;
    int a0 = at * 32;
    int kbase = ks * 256;
    int zr = step & 1;
    int al = tid >> 3, bq = (tid & 7) << 2;
    int bbz = tid >> 3, kk0 = tid & 7;
    const float* zsrc = g_z[zr];
    float a0v = 0.f, a1v = 0.f, a2v = 0.f, a3v = 0.f;
    for (int kc = 0; kc < 4; kc++) {
        int k0 = kbase + kc * 64;
        __syncthreads();
#pragma unroll
        for (int i = 0; i < 2; i++) {
            int lin = tid + (i << 8);
            int row = lin >> 4, kq = (lin & 15) << 2;
            float4 w4 = *(const float4*)(w_dec + (size_t)(a0 + row) * DD + k0 + kq);
            ws2[row][kq + 0] = w4.x; ws2[row][kq + 1] = w4.y;
            ws2[row][kq + 2] = w4.z; ws2[row][kq + 3] = w4.w;
        }
#pragma unroll
        for (int j = 0; j < 8; j++) {
            int kk = kk0 + (j << 3);
            zs[kk][bbz] = zsrc[bbz * DD + k0 + kk];
        }
        __syncthreads();
#pragma unroll
        for (int kk = 0; kk < 64; kk++) {
            float w = ws2[al][kk];
            float4 x = *(const float4*)&zs[kk][bq];
            a0v = fmaf(w, x.x, a0v); a1v = fmaf(w, x.y, a1v);
            a2v = fmaf(w, x.z, a2v); a3v = fmaf(w, x.w, a3v);
        }
    }
    g_decp[ks][(bq + 0) * AA + a0 + al] = a0v;
    g_decp[ks][(bq + 1) * AA + a0 + al] = a1v;
    g_decp[ks][(bq + 2) * AA + a0 + al] = a2v;
    g_decp[ks][(bq + 3) * AA + a0 + al] = a3v;
}

// ---------- per-step: fused conv + e + exp, t-chunk 24, 8-deep load batches ----------
__global__ __launch_bounds__(128) void k_e(const float* __restrict__ w_gvec,
                                           const float* __restrict__ w_conv) {
    int b = blockIdx.y, t0 = blockIdx.x * TCH;
    int tid = threadIdx.x;
    __shared__ float wk[CC * KW];          // 2010 f
    __shared__ float aw_s[TCH + 2 * FF];   // 224 f
    __shared__ __half2 conv_s2[TCH][10];
    __shared__ float part_s[TCH][4];
    __shared__ float exps[TCH];
    // load conv weights + aw slice
    for (int i = tid; i < CC * KW; i += 128) wk[i] = w_conv[i];
    for (int i = tid; i < TCH + 2 * FF; i += 128) {
        int t = t0 - FF + i;
        aw_s[i] = (t >= 0 && t < TT) ? g_aw[b * TT + t] : 0.f;
    }
    __syncthreads();
    // conv: 240 (tl,c) pairs over 128 threads
    for (int p = tid; p < TCH * CC; p += 128) {
        int tl = p / CC, c = p - tl * CC;
        const float* wkc = wk + c * KW;
        float s = 0.f;
#pragma unroll 4
        for (int k = 0; k < KW; k++) s = fmaf(wkc[k], aw_s[tl + k], s);
        conv_s2[tl][c] = __float2half2_rn(s);
    }
    int a0 = tid * 4, p0 = tid * 2;
    __half2 wr2[2][10];
    float gg[4], dcf[4];
#pragma unroll
    for (int pp = 0; pp < 2; pp++)
#pragma unroll
        for (int c = 0; c < 10; c++) wr2[pp][c] = g_wattp[(c << 8) + p0 + pp];
#pragma unroll
    for (int j = 0; j < 4; j++) {
        gg[j] = w_gvec[a0 + j];
        int ai = b * AA + a0 + j;
        dcf[j] = g_decp[0][ai] + g_decp[1][ai] + g_decp[2][ai] + g_decp[3][ai];
    }
    __half2 dch0 = __floats2half2_rn(dcf[0], dcf[1]);
    __half2 dch1 = __floats2half2_rn(dcf[2], dcf[3]);
    __syncthreads();
    int lane = tid & 31, warp = tid >> 5;
    const __half2* prep = (const __half2*)(g_preh + (size_t)b * TT * AA + a0);
    for (int tq = 0; tq < TCH; tq += 8) {
        uint2 u[8];
#pragma unroll
        for (int q = 0; q < 8; q++) {
            int t = t0 + tq + q;
            if (t > TT - 1) t = TT - 1;
            u[q] = *(const uint2*)(prep + (size_t)t * (AA / 2));
        }
        float acc[8];
#pragma unroll
        for (int q = 0; q < 8; q++) {
            __half2 pa0 = *reinterpret_cast<__half2*>(&u[q].x);
            __half2 pa1 = *reinterpret_cast<__half2*>(&u[q].y);
            __half2 x0 = __hadd2(pa0, dch0);
            __half2 x1 = __hadd2(pa1, dch1);
#pragma unroll
            for (int c = 0; c < 10; c++) {
                __half2 cvt = conv_s2[tq + q][c];
                x0 = __hfma2(cvt, wr2[0][c], x0);
                x1 = __hfma2(cvt, wr2[1][c], x1);
            }
            float2 f0 = __half22float2(tanh2(x0));
            float2 f1 = __half22float2(tanh2(x1));
            acc[q] = gg[0] * f0.x + gg[1] * f0.y + gg[2] * f1.x + gg[3] * f1.y;
        }
#pragma unroll
        for (int s = 16; s; s >>= 1) {
#pragma unroll
            for (int q = 0; q < 8; q++)
                acc[q] += __shfl_xor_sync(0xffffffffu, acc[q], s);
        }
        if (lane == 0) {
#pragma unroll
            for (int q = 0; q < 8; q++) part_s[tq + q][warp] = acc[q];
        }
    }
    __syncthreads();
    if (tid < TCH) {
        int t = t0 + tid;
        float e = part_s[tid][0] + part_s[tid][1] + part_s[tid][2] + part_s[tid][3];
        float ex = (t < TT) ? __expf(2.f * e) : 0.f;
        if (t < TT) g_e[b * TT + t] = ex;
        exps[tid] = ex;
    }
    __syncthreads();
    if (tid == 0) {
        float s = 0.f;
#pragma unroll
        for (int i = 0; i < TCH; i++) s += exps[i];
        g_epart[b * NTC + blockIdx.x] = s;
    }
}

// ---------- per-step: normalize + ctx partials (uint4 loads) + aw ----------
__global__ __launch_bounds__(256) void k_ctx() {
    int b = blockIdx.y;
    int ec = blockIdx.x & 3, tc = blockIdx.x >> 2;
    int tid = threadIdx.x;
    __shared__ float wsm[500];
    __shared__ float sred[64];
    __shared__ float racc[256 * 8];
    if (tid < 64) sred[tid] = (tid < NTC) ? g_epart[b * NTC + tid] : 0.f;
    __syncthreads();
    if (tid < 32) {
        float v = sred[tid] + sred[tid + 32];
#pragma unroll
        for (int s = 16; s; s >>= 1) v += __shfl_xor_sync(0xffffffffu, v, s);
        if (tid == 0) sred[0] = v;
    }
    __syncthreads();
    float inv = 1.f / sred[0];
    int tbase = tc * 500;
    for (int i = tid; i < 500; i += 256) {
        float w = g_e[b * TT + tbase + i] * inv;
        wsm[i] = w;
        if (ec == 0) g_aw[b * TT + tbase + i] = w;
    }
    __syncthreads();
    int eg = tid & 15, ts = tid >> 4;          // 16 e-groups of 8, 16 t-subs
    int e0 = ec * 128 + eg * 8;
    int tsub0 = ts * 31;
    int cnt = (ts == 15) ? 35 : 31;            // 500 = 15*31 + 35
    const uint4* hp = (const uint4*)(g_hpadh + ((size_t)b * TT + tbase + tsub0) * EE + e0);
    float a[8];
#pragma unroll
    for (int j = 0; j < 8; j++) a[j] = 0.f;
#pragma unroll 4
    for (int i = 0; i < cnt; i++) {
        uint4 u = __ldcs(hp + (size_t)i * (EE / 8));
        __half2* h2 = (__half2*)&u;
        float w = wsm[tsub0 + i];
#pragma unroll
        for (int q = 0; q < 4; q++) {
            float2 f = __half22float2(h2[q]);
            a[q * 2 + 0] = fmaf(w, f.x, a[q * 2 + 0]);
            a[q * 2 + 1] = fmaf(w, f.y, a[q * 2 + 1]);
        }
    }
#pragma unroll
    for (int j = 0; j < 8; j++) racc[tid * 8 + j] = a[j];
    __syncthreads();
    if (tid < 128) {
        int eg2 = tid >> 3, j = tid & 7;
        float s = 0.f;
#pragma unroll
        for (int ts2 = 0; ts2 < 16; ts2++) s += racc[(ts2 * 16 + eg2) * 8 + j];
        g_ctxp2[tc][b * EE + ec * 128 + eg2 * 8 + j] = s;
    }
}

// ---------- per-step: LSTM gates + cell ----------
__global__ __launch_bounds__(128) void k_lstm(int step) {
    __shared__ float ws[16][68];
    __shared__ float xs[64][36];
    __shared__ float gates_s[16][33];
    int tid = threadIdx.x;
    int r0 = blockIdx.x * 16;
    int zr = step & 1;
    int rl = tid >> 3, b0 = (tid & 7) << 2;
    int bb = tid >> 2, kk0 = tid & 3;
    float acc0 = __ldcs(&g_gey[(size_t)(step * BB + b0 + 0) * NROW + r0 + rl]);
    float acc1 = __ldcs(&g_gey[(size_t)(step * BB + b0 + 1) * NROW + r0 + rl]);
    float acc2 = __ldcs(&g_gey[(size_t)(step * BB + b0 + 2) * NROW + r0 + rl]);
    float acc3 = __ldcs(&g_gey[(size_t)(step * BB + b0 + 3) * NROW + r0 + rl]);
    const float* zsrc = g_z[zr];
    int wrow = tid >> 3, wkq = (tid & 7) << 3;
    for (int k0 = 0; k0 < KCAT2; k0 += 64) {
        {
            uint4 w8 = *(const uint4*)(g_wcat2h + (size_t)(r0 + wrow) * KCAT2 + k0 + wkq);
            __half2* hp = (__half2*)&w8;
            float2 f0 = __half22float2(hp[0]);
            float2 f1 = __half22float2(hp[1]);
            float2 f2 = __half22float2(hp[2]);
            float2 f3 = __half22float2(hp[3]);
            ws[wrow][wkq + 0] = f0.x; ws[wrow][wkq + 1] = f0.y;
            ws[wrow][wkq + 2] = f1.x; ws[wrow][wkq + 3] = f1.y;
            ws[wrow][wkq + 4] = f2.x; ws[wrow][wkq + 5] = f2.y;
            ws[wrow][wkq + 6] = f3.x; ws[wrow][wkq + 7] = f3.y;
        }
#pragma unroll
        for (int j = 0; j < 16; j++) {
            int kk = kk0 + (j << 2);
            int k = k0 + kk;
            float v;
            if (k < EE) {
                int ci = bb * EE + k;
                v = g_ctxp2[0][ci] + g_ctxp2[1][ci];
            } else v = zsrc[bb * DD + (k - EE)];
            xs[kk][bb] = v;
        }
        __syncthreads();
#pragma unroll
        for (int kk = 0; kk < 64; kk++) {
            float w = ws[rl][kk];
            float4 x = *(const float4*)&xs[kk][b0];
            acc0 = fmaf(w, x.x, acc0); acc1 = fmaf(w, x.y, acc1);
            acc2 = fmaf(w, x.z, acc2); acc3 = fmaf(w, x.w, acc3);
        }
        __syncthreads();
    }
    gates_s[rl][b0 + 0] = acc0;
    gates_s[rl][b0 + 1] = acc1;
    gates_s[rl][b0 + 2] = acc2;
    gates_s[rl][b0 + 3] = acc3;
    __syncthreads();
    int dl = tid >> 5, b = tid & 31;
    int d = (r0 >> 2) + dl;
    float iv = gates_s[dl * 4 + 0][b];
    float fv = gates_s[dl * 4 + 1][b];
    float gv = gates_s[dl * 4 + 2][b];
    float ov = gates_s[dl * 4 + 3][b];
    float si = 1.f / (1.f + expf(-iv));
    float sf = 1.f / (1.f + expf(-fv));
    float so = 1.f / (1.f + expf(-ov));
    float cn = sf * g_c[b * DD + d] + si * tanhf(gv);
    float zn = so * tanhf(cn);
    g_c[b * DD + d] = cn;
    g_z[zr ^ 1][b * DD + d] = zn;
    __stcs(&g_zall[(size_t)(step * BB + b) * DD + d], zn);
}

// ---------- final: out = z_all @ w_out^T + b_out ----------
__global__ __launch_bounds__(256) void k_out(const float* __restrict__ Bm,
                                             const float* __restrict__ bias,
                                             float* __restrict__ Cout) {
    __shared__ float As[16][132];
    __shared__ float Bs[16][132];
    int tid = threadIdx.x;
    int m0 = blockIdx.y * 128, n0 = blockIdx.x * 128;
    float acc[8][8];
#pragma unroll
    for (int i = 0; i < 8; i++)
#pragma unroll
        for (int j = 0; j < 8; j++) acc[i][j] = 0.f;
    int tm0 = (tid >> 4) << 3, tn0 = (tid & 15) << 3;
    for (int k0 = 0; k0 < DD; k0 += 16) {
#pragma unroll
        for (int i = 0; i < 2; i++) {
            int lin = tid + (i << 8);
            int row = lin >> 2, kq = (lin & 3) << 2;
            float4 va = *(const float4*)(g_zall + (size_t)(m0 + row) * DD + k0 + kq);
            As[kq + 0][row] = va.x; As[kq + 1][row] = va.y;
            As[kq + 2][row] = va.z; As[kq + 3][row] = va.w;
            int nr = n0 + row;
            float4 vb = make_float4(0.f, 0.f, 0.f, 0.f);
            if (nr < ODIM_) vb = *(const float4*)(Bm + (size_t)nr * DD + k0 + kq);
            Bs[kq + 0][row] = vb.x; Bs[kq + 1][row] = vb.y;
            Bs[kq + 2][row] = vb.z; Bs[kq + 3][row] = vb.w;
        }
        __syncthreads();
#pragma unroll
        for (int kk = 0; kk < 16; kk++) {
            float a[8], b[8];
            *(float4*)&a[0] = *(const float4*)&As[kk][tm0];
            *(float4*)&a[4] = *(const float4*)&As[kk][tm0 + 4];
            *(float4*)&b[0] = *(const float4*)&Bs[kk][tn0];
            *(float4*)&b[4] = *(const float4*)&Bs[kk][tn0 + 4];
#pragma unroll
            for (int i = 0; i < 8; i++)
#pragma unroll
                for (int j = 0; j < 8; j++)
                    acc[i][j] = fmaf(a[i], b[j], acc[i][j]);
        }
        __syncthreads();
    }
#pragma unroll
    for (int i = 0; i < 8; i++) {
        int m_ = m0 + tm0 + i;
        if (m_ >= MOUT) continue;
        int b_ = m_ & 31, o_ = m_ >> 5;
#pragma unroll
        for (int j = 0; j < 8; j++) {
            int n_ = n0 + tn0 + j;
            if (n_ >= ODIM_) continue;
            Cout[(size_t)(b_ * OLEN + o_) * ODIM_ + n_] = acc[i][j] + bias[n_];
        }
    }
}

extern "C" void kernel_launch(void* const* d_in, const int* in_sizes, int n_in,
                              void* d_out, int out_size) {
    const float* hpad   = (const float*)d_in[0];
    const int*   ys     = (const int*)d_in[1];
    const float* w_enc  = (const float*)d_in[2];
    const float* b_enc  = (const float*)d_in[3];
    const float* w_dec  = (const float*)d_in[4];
    const float* w_att  = (const float*)d_in[5];
    const float* w_conv = (const float*)d_in[6];
    const float* w_gvec = (const float*)d_in[7];
    const float* embed  = (const float*)d_in[9];
    const float* w_ih   = (const float*)d_in[10];
    const float* w_hh   = (const float*)d_in[11];
    const float* b_ih   = (const float*)d_in[12];
    const float* b_hh   = (const float*)d_in[13];
    const float* w_out  = (const float*)d_in[14];
    const float* b_out  = (const float*)d_in[15];
    float* out = (float*)d_out;

    k_prep<<<8192, 256>>>(w_ih, w_hh, hpad, w_att);
    k_gemms<<<1832, 256>>>(hpad, w_enc, b_enc, w_ih, b_ih, b_hh, ys, embed);

    for (int step = 0; step < OLEN; step++) {
        k_dec<<<64, 256>>>(w_dec, step);
        k_e<<<dim3(NTC, BB), 128>>>(w_gvec, w_conv);
        k_ctx<<<dim3(8, BB), 256>>>();
        k_lstm<<<256, 128>>>(step);
    }
    k_out<<<dim3(40, 26), 256>>>(w_out, b_out, out);
}

// round 12
// speedup vs baseline: 1.0416x; 1.0416x over previous
#include <cuda_runtime.h>
#include <cuda_fp16.h>

#define BB 32
#define TT 1000
#define EE 512
#define DD 1024
#define AA 512
#define CC 10
#define FF 100
#define KW 201
#define ODIM_ 5000
#define LL 100
#define OLEN 101
#define SOS_ 4998
#define NROW 4096
#define KCAT2 1536
#define MOUT 3232
#define MOUT_PAD 3328

__device__ __half g_preh[BB * TT * AA];          // 32.8 MB
__device__ __half g_hpadh[BB * TT * EE];         // 32.8 MB
__device__ __half g_wcat2h[NROW * KCAT2];        // 12.6 MB
__device__ float g_gey[MOUT_PAD * NROW];         // 54.5 MB (streamed)
__device__ __half2 g_wattp[10 * 256];
__device__ float g_aw[BB * TT];
__device__ float g_e[BB * TT];                   // exp(2e)
__device__ float g_epart[BB * 50];
__device__ float g_conv[BB * CC * TT];
__device__ float g_decp[4][BB * AA];
__device__ float g_ctxp2[2][BB * EE];
__device__ float g_z[2][BB * DD];
__device__ float g_c[BB * DD];
__device__ float g_zall[MOUT_PAD * DD];

__device__ __forceinline__ __half2 tanh2(__half2 x) {
    unsigned xi = *reinterpret_cast<unsigned*>(&x), yi;
    asm("tanh.approx.f16x2 %0, %1;" : "=r"(yi) : "r"(xi));
    return *reinterpret_cast<__half2*>(&yi);
}

// ---------- pre-loop kernel 1 ----------
__global__ void k_prep(const float* __restrict__ w_ih, const float* __restrict__ w_hh,
                       const float* __restrict__ hpad, const float* __restrict__ w_att) {
    const size_t TOT = 22742784;
    for (size_t i = (size_t)blockIdx.x * 256 + threadIdx.x; i < TOT; i += 2097152) {
        if (i < 32768) {
            g_z[0][i] = 0.f; g_c[i] = 0.f;
        } else if (i < 64768) {
            g_aw[i - 32768] = 1.0f / TT;
        } else if (i < 6356224) {
            int j = (int)(i - 64768);
            int r = j / KCAT2, k = j - r * KCAT2;
            int n = (r & 3) * DD + (r >> 2);
            float v = (k < EE) ? w_ih[(size_t)n * (DD + EE) + DD + k]
                               : w_hh[(size_t)n * DD + (k - EE)];
            g_wcat2h[j] = __float2half(v);
        } else if (i < 22740224) {
            size_t j = i - 6356224;
            g_hpadh[j] = __float2half(hpad[j]);
        } else {
            int j = (int)(i - 22740224);
            int c = j >> 8, p = j & 255;
            g_wattp[j] = __floats2half2_rn(w_att[(2 * p) * CC + c],
                                           w_att[(2 * p + 1) * CC + c]);
        }
    }
}

// ---------- pre-loop kernel 2: fused one-time GEMMs ----------
__global__ __launch_bounds__(256) void k_gemms(const float* __restrict__ hpad,
                                               const float* __restrict__ w_enc,
                                               const float* __restrict__ b_enc,
                                               const float* __restrict__ w_ih,
                                               const float* __restrict__ b_ih,
                                               const float* __restrict__ b_hh,
                                               const int* __restrict__ ys,
                                               const float* __restrict__ embed) {
    __shared__ float As[16][132];
    __shared__ float Bs[16][132];
    __shared__ int tok_s[128];
    int tid = threadIdx.x;
    bool is_pre = blockIdx.x >= 832;
    int m0, n0, K;
    if (is_pre) {
        int idx = blockIdx.x - 832;
        m0 = (idx >> 2) * 128; n0 = (idx & 3) * 128; K = 512;
    } else {
        m0 = ((int)blockIdx.x >> 5) * 128; n0 = ((int)blockIdx.x & 31) * 128; K = 1024;
        if (tid < 128) {
            int m = m0 + tid;
            int s = m >> 5, b = m & 31;
            tok_s[tid] = (s == 0 || s > 100) ? SOS_ : ys[b * LL + s - 1];
        }
        __syncthreads();
    }
    float acc[8][8];
#pragma unroll
    for (int i = 0; i < 8; i++)
#pragma unroll
        for (int j = 0; j < 8; j++) acc[i][j] = 0.f;
    int tm0 = (tid >> 4) << 3, tn0 = (tid & 15) << 3;
    for (int k0 = 0; k0 < K; k0 += 16) {
#pragma unroll
        for (int i = 0; i < 2; i++) {
            int lin = tid + (i << 8);
            int row = lin >> 2, kq = (lin & 3) << 2;
            float4 va, vb;
            if (is_pre) {
                va = *(const float4*)(hpad + (size_t)(m0 + row) * 512 + k0 + kq);
                vb = *(const float4*)(w_enc + (size_t)(n0 + row) * 512 + k0 + kq);
            } else {
                va = *(const float4*)(embed + (size_t)tok_s[row] * DD + k0 + kq);
                int r = n0 + row;
                int orig = (r & 3) * DD + (r >> 2);
                vb = *(const float4*)(w_ih + (size_t)orig * (DD + EE) + k0 + kq);
            }
            As[kq + 0][row] = va.x; As[kq + 1][row] = va.y;
            As[kq + 2][row] = va.z; As[kq + 3][row] = va.w;
            Bs[kq + 0][row] = vb.x; Bs[kq + 1][row] = vb.y;
            Bs[kq + 2][row] = vb.z; Bs[kq + 3][row] = vb.w;
        }
        __syncthreads();
#pragma unroll
        for (int kk = 0; kk < 16; kk++) {
            float a[8], b[8];
            *(float4*)&a[0] = *(const float4*)&As[kk][tm0];
            *(float4*)&a[4] = *(const float4*)&As[kk][tm0 + 4];
            *(float4*)&b[0] = *(const float4*)&Bs[kk][tn0];
            *(float4*)&b[4] = *(const float4*)&Bs[kk][tn0 + 4];
#pragma unroll
            for (int i = 0; i < 8; i++)
#pragma unroll
                for (int j = 0; j < 8; j++)
                    acc[i][j] = fmaf(a[i], b[j], acc[i][j]);
        }
        __syncthreads();
    }
#pragma unroll
    for (int i = 0; i < 8; i++) {
        int m_ = m0 + tm0 + i;
#pragma unroll
        for (int j = 0; j < 8; j++) {
            int n_ = n0 + tn0 + j;
            if (is_pre) {
                g_preh[(size_t)m_ * 512 + n_] = __float2half(acc[i][j] + b_enc[n_]);
            } else {
                int orig = (n_ & 3) * DD + (n_ >> 2);
                __stcs(&g_gey[(size_t)m_ * NROW + n_], acc[i][j] + b_ih[orig] + b_hh[orig]);
            }
        }
    }
}

// ---------- per-step: conv(aw) [0..319] + dec GEMM K-split [320..383] ----------
__global__ __launch_bounds__(256) void k_small(const float* __restrict__ w_dec,
                                               const float* __restrict__ w_conv, int step) {
    int blk = blockIdx.x, tid = threadIdx.x;
    if (blk < BB * CC) {
        __shared__ float sm[1408];
        int b = blk / CC, c = blk - b * CC;
        float* aw_s = sm;
        float* wk = sm + 1200;
        for (int i = tid; i < TT + 2 * FF; i += 256)
            aw_s[i] = (i >= FF && i < FF + TT) ? g_aw[b * TT + i - FF] : 0.f;
        for (int i = tid; i < KW; i += 256) wk[i] = w_conv[c * KW + i];
        __syncthreads();
        for (int t = tid; t < TT; t += 256) {
            float s = 0.f;
#pragma unroll 4
            for (int k = 0; k < KW; k++) s = fmaf(wk[k], aw_s[t + k], s);
            g_conv[(b * CC + c) * TT + t] = s;
        }
    } else {
        __shared__ float ws2[32][68];
        __shared__ float zs[64][36];
        int blk2 = blk - BB * CC;
        int ks = blk2 & 3, at = blk2 >> 2;
        int a0 = at * 32;
        int kbase = ks * 256;
        int zr = step & 1;
        int al = tid >> 3, bq = (tid & 7) << 2;
        int bbz = tid >> 3, kk0 = tid & 7;
        const float* zsrc = g_z[zr];
        float a0v = 0.f, a1v = 0.f, a2v = 0.f, a3v = 0.f;
        for (int kc = 0; kc < 4; kc++) {
            int k0 = kbase + kc * 64;
            __syncthreads();
#pragma unroll
            for (int i = 0; i < 2; i++) {
                int lin = tid + (i << 8);
                int row = lin >> 4, kq = (lin & 15) << 2;
                float4 w4 = *(const float4*)(w_dec + (size_t)(a0 + row) * DD + k0 + kq);
                ws2[row][kq + 0] = w4.x; ws2[row][kq + 1] = w4.y;
                ws2[row][kq + 2] = w4.z; ws2[row][kq + 3] = w4.w;
            }
#pragma unroll
            for (int j = 0; j < 8; j++) {
                int kk = kk0 + (j << 3);
                zs[kk][bbz] = zsrc[bbz * DD + k0 + kk];
            }
            __syncthreads();
#pragma unroll
            for (int kk = 0; kk < 64; kk++) {
                float w = ws2[al][kk];
                float4 x = *(const float4*)&zs[kk][bq];
                a0v = fmaf(w, x.x, a0v); a1v = fmaf(w, x.y, a1v);
                a2v = fmaf(w, x.z, a2v); a3v = fmaf(w, x.w, a3v);
            }
        }
        g_decp[ks][(bq + 0) * AA + a0 + al] = a0v;
        g_decp[ks][(bq + 1) * AA + a0 + al] = a1v;
        g_decp[ks][(bq + 2) * AA + a0 + al] = a2v;
        g_decp[ks][(bq + 3) * AA + a0 + al] = a3v;
    }
}

// ---------- per-step: exp(2*e[b,t]) half2 math, 10-deep load batches ----------
__global__ __launch_bounds__(128) void k_e(const float* __restrict__ w_gvec) {
    int b = blockIdx.y, t0 = blockIdx.x * 20;
    int tid = threadIdx.x;
    __shared__ __half2 conv_s2[20][10];
    __shared__ float part_s[20][4];
    __shared__ float exps[20];
    for (int i = tid; i < 200; i += 128) {
        int c = i / 20, tl = i - c * 20;
        conv_s2[tl][c] = __float2half2_rn(g_conv[(b * CC + c) * TT + t0 + tl]);
    }
    int a0 = tid * 4, p0 = tid * 2;
    __half2 wr2[2][10];
    float gg[4], dcf[4];
#pragma unroll
    for (int pp = 0; pp < 2; pp++)
#pragma unroll
        for (int c = 0; c < 10; c++) wr2[pp][c] = g_wattp[(c << 8) + p0 + pp];
#pragma unroll
    for (int j = 0; j < 4; j++) {
        gg[j] = w_gvec[a0 + j];
        int ai = b * AA + a0 + j;
        dcf[j] = g_decp[0][ai] + g_decp[1][ai] + g_decp[2][ai] + g_decp[3][ai];
    }
    __half2 dch0 = __floats2half2_rn(dcf[0], dcf[1]);
    __half2 dch1 = __floats2half2_rn(dcf[2], dcf[3]);
    __syncthreads();
    int lane = tid & 31, warp = tid >> 5;
    const __half2* prep = (const __half2*)(g_preh + ((size_t)b * TT + t0) * AA + a0);
    for (int tq = 0; tq < 20; tq += 10) {
        uint2 u[10];
#pragma unroll
        for (int q = 0; q < 10; q++)
            u[q] = *(const uint2*)(prep + (size_t)(tq + q) * (AA / 2));
        float acc[10];
#pragma unroll
        for (int q = 0; q < 10; q++) {
            __half2 pa0 = *reinterpret_cast<__half2*>(&u[q].x);
            __half2 pa1 = *reinterpret_cast<__half2*>(&u[q].y);
            __half2 x0 = __hadd2(pa0, dch0);
            __half2 x1 = __hadd2(pa1, dch1);
#pragma unroll
            for (int c = 0; c < 10; c++) {
                __half2 cvt = conv_s2[tq + q][c];
                x0 = __hfma2(cvt, wr2[0][c], x0);
                x1 = __hfma2(cvt, wr2[1][c], x1);
            }
            float2 f0 = __half22float2(tanh2(x0));
            float2 f1 = __half22float2(tanh2(x1));
            acc[q] = gg[0] * f0.x + gg[1] * f0.y + gg[2] * f1.x + gg[3] * f1.y;
        }
#pragma unroll
        for (int s = 16; s; s >>= 1) {
#pragma unroll
            for (int q = 0; q < 10; q++)
                acc[q] += __shfl_xor_sync(0xffffffffu, acc[q], s);
        }
        if (lane == 0) {
#pragma unroll
            for (int q = 0; q < 10; q++) part_s[tq + q][warp] = acc[q];
        }
    }
    __syncthreads();
    if (tid < 20) {
        float e = part_s[tid][0] + part_s[tid][1] + part_s[tid][2] + part_s[tid][3];
        float ex = __expf(2.f * e);          // no-max softmax: |e| <= ~8, safe
        g_e[b * TT + t0 + tid] = ex;
        exps[tid] = ex;
    }
    __syncthreads();
    if (tid == 0) {
        float s = 0.f;
#pragma unroll
        for (int i = 0; i < 20; i++) s += exps[i];
        g_epart[b * 50 + blockIdx.x] = s;
    }
}

// ---------- per-step: normalize + ctx partials (uint4 ldcs loads) + aw ----------
__global__ __launch_bounds__(256) void k_ctx() {
    int b = blockIdx.y;
    int ec = blockIdx.x & 3, tc = blockIdx.x >> 2;
    int tid = threadIdx.x;
    __shared__ float wsm[500];
    __shared__ float sred[64];
    __shared__ float racc[256 * 8];
    if (tid < 64) sred[tid] = (tid < 50) ? g_epart[b * 50 + tid] : 0.f;
    __syncthreads();
    if (tid < 32) {
        float v = sred[tid] + sred[tid + 32];
#pragma unroll
        for (int s = 16; s; s >>= 1) v += __shfl_xor_sync(0xffffffffu, v, s);
        if (tid == 0) sred[0] = v;
    }
    __syncthreads();
    float inv = 1.f / sred[0];
    int tbase = tc * 500;
    for (int i = tid; i < 500; i += 256) {
        float w = g_e[b * TT + tbase + i] * inv;
        wsm[i] = w;
        if (ec == 0) g_aw[b * TT + tbase + i] = w;
    }
    __syncthreads();
    int eg = tid & 15, ts = tid >> 4;          // 16 e-groups of 8, 16 t-subs
    int e0 = ec * 128 + eg * 8;
    int tsub0 = ts * 31;
    int cnt = (ts == 15) ? 35 : 31;            // 500 = 15*31 + 35
    const uint4* hp = (const uint4*)(g_hpadh + ((size_t)b * TT + tbase + tsub0) * EE + e0);
    float a[8];
#pragma unroll
    for (int j = 0; j < 8; j++) a[j] = 0.f;
#pragma unroll 4
    for (int i = 0; i < cnt; i++) {
        uint4 u = __ldcs(hp + (size_t)i * (EE / 8));
        __half2* h2 = (__half2*)&u;
        float w = wsm[tsub0 + i];
#pragma unroll
        for (int q = 0; q < 4; q++) {
            float2 f = __half22float2(h2[q]);
            a[q * 2 + 0] = fmaf(w, f.x, a[q * 2 + 0]);
            a[q * 2 + 1] = fmaf(w, f.y, a[q * 2 + 1]);
        }
    }
#pragma unroll
    for (int j = 0; j < 8; j++) racc[tid * 8 + j] = a[j];
    __syncthreads();
    if (tid < 128) {
        int eg2 = tid >> 3, j = tid & 7;
        float s = 0.f;
#pragma unroll
        for (int ts2 = 0; ts2 < 16; ts2++) s += racc[(ts2 * 16 + eg2) * 8 + j];
        g_ctxp2[tc][b * EE + ec * 128 + eg2 * 8 + j] = s;
    }
}

// ---------- per-step: LSTM gates (fp16 weights, r-tile 16, 256 blocks) + cell ----------
__global__ __launch_bounds__(128) void k_lstm(int step) {
    __shared__ float ws[16][68];
    __shared__ float xs[64][36];
    __shared__ float gates_s[16][33];
    int tid = threadIdx.x;
    int r0 = blockIdx.x * 16;
    int zr = step & 1;
    int rl = tid >> 3, b0 = (tid & 7) << 2;
    int bb = tid >> 2, kk0 = tid & 3;
    float acc0 = __ldcs(&g_gey[(size_t)(step * BB + b0 + 0) * NROW + r0 + rl]);
    float acc1 = __ldcs(&g_gey[(size_t)(step * BB + b0 + 1) * NROW + r0 + rl]);
    float acc2 = __ldcs(&g_gey[(size_t)(step * BB + b0 + 2) * NROW + r0 + rl]);
    float acc3 = __ldcs(&g_gey[(size_t)(step * BB + b0 + 3) * NROW + r0 + rl]);
    const float* zsrc = g_z[zr];
    int wrow = tid >> 3, wkq = (tid & 7) << 3;
    for (int k0 = 0; k0 < KCAT2; k0 += 64) {
        {
            uint4 w8 = *(const uint4*)(g_wcat2h + (size_t)(r0 + wrow) * KCAT2 + k0 + wkq);
            __half2* hp = (__half2*)&w8;
            float2 f0 = __half22float2(hp[0]);
            float2 f1 = __half22float2(hp[1]);
            float2 f2 = __half22float2(hp[2]);
            float2 f3 = __half22float2(hp[3]);
            ws[wrow][wkq + 0] = f0.x; ws[wrow][wkq + 1] = f0.y;
            ws[wrow][wkq + 2] = f1.x; ws[wrow][wkq + 3] = f1.y;
            ws[wrow][wkq + 4] = f2.x; ws[wrow][wkq + 5] = f2.y;
            ws[wrow][wkq + 6] = f3.x; ws[wrow][wkq + 7] = f3.y;
        }
#pragma unroll
        for (int j = 0; j < 16; j++) {
            int kk = kk0 + (j << 2);
            int k = k0 + kk;
            float v;
            if (k < EE) {
                int ci = bb * EE + k;
                v = g_ctxp2[0][ci] + g_ctxp2[1][ci];
            } else v = zsrc[bb * DD + (k - EE)];
            xs[kk][bb] = v;
        }
        __syncthreads();
#pragma unroll
        for (int kk = 0; kk < 64; kk++) {
            float w = ws[rl][kk];
            float4 x = *(const float4*)&xs[kk][b0];
            acc0 = fmaf(w, x.x, acc0); acc1 = fmaf(w, x.y, acc1);
            acc2 = fmaf(w, x.z, acc2); acc3 = fmaf(w, x.w, acc3);
        }
        __syncthreads();
    }
    gates_s[rl][b0 + 0] = acc0;
    gates_s[rl][b0 + 1] = acc1;
    gates_s[rl][b0 + 2] = acc2;
    gates_s[rl][b0 + 3] = acc3;
    __syncthreads();
    int dl = tid >> 5, b = tid & 31;
    int d = (r0 >> 2) + dl;
    float iv = gates_s[dl * 4 + 0][b];
    float fv = gates_s[dl * 4 + 1][b];
    float gv = gates_s[dl * 4 + 2][b];
    float ov = gates_s[dl * 4 + 3][b];
    float si = 1.f / (1.f + expf(-iv));
    float sf = 1.f / (1.f + expf(-fv));
    float so = 1.f / (1.f + expf(-ov));
    float cn = sf * g_c[b * DD + d] + si * tanhf(gv);
    float zn = so * tanhf(cn);
    g_c[b * DD + d] = cn;
    g_z[zr ^ 1][b * DD + d] = zn;
    __stcs(&g_zall[(size_t)(step * BB + b) * DD + d], zn);
}

// ---------- final: out = z_all @ w_out^T + b_out ----------
__global__ __launch_bounds__(256) void k_out(const float* __restrict__ Bm,
                                             const float* __restrict__ bias,
                                             float* __restrict__ Cout) {
    __shared__ float As[16][132];
    __shared__ float Bs[16][132];
    int tid = threadIdx.x;
    int m0 = blockIdx.y * 128, n0 = blockIdx.x * 128;
    float acc[8][8];
#pragma unroll
    for (int i = 0; i < 8; i++)
#pragma unroll
        for (int j = 0; j < 8; j++) acc[i][j] = 0.f;
    int tm0 = (tid >> 4) << 3, tn0 = (tid & 15) << 3;
    for (int k0 = 0; k0 < DD; k0 += 16) {
#pragma unroll
        for (int i = 0; i < 2; i++) {
            int lin = tid + (i << 8);
            int row = lin >> 2, kq = (lin & 3) << 2;
            float4 va = *(const float4*)(g_zall + (size_t)(m0 + row) * DD + k0 + kq);
            As[kq + 0][row] = va.x; As[kq + 1][row] = va.y;
            As[kq + 2][row] = va.z; As[kq + 3][row] = va.w;
            int nr = n0 + row;
            float4 vb = make_float4(0.f, 0.f, 0.f, 0.f);
            if (nr < ODIM_) vb = *(const float4*)(Bm + (size_t)nr * DD + k0 + kq);
            Bs[kq + 0][row] = vb.x; Bs[kq + 1][row] = vb.y;
            Bs[kq + 2][row] = vb.z; Bs[kq + 3][row] = vb.w;
        }
        __syncthreads();
#pragma unroll
        for (int kk = 0; kk < 16; kk++) {
            float a[8], b[8];
            *(float4*)&a[0] = *(const float4*)&As[kk][tm0];
            *(float4*)&a[4] = *(const float4*)&As[kk][tm0 + 4];
            *(float4*)&b[0] = *(const float4*)&Bs[kk][tn0];
            *(float4*)&b[4] = *(const float4*)&Bs[kk][tn0 + 4];
#pragma unroll
            for (int i = 0; i < 8; i++)
#pragma unroll
                for (int j = 0; j < 8; j++)
                    acc[i][j] = fmaf(a[i], b[j], acc[i][j]);
        }
        __syncthreads();
    }
#pragma unroll
    for (int i = 0; i < 8; i++) {
        int m_ = m0 + tm0 + i;
        if (m_ >= MOUT) continue;
        int b_ = m_ & 31, o_ = m_ >> 5;
#pragma unroll
        for (int j = 0; j < 8; j++) {
            int n_ = n0 + tn0 + j;
            if (n_ >= ODIM_) continue;
            Cout[(size_t)(b_ * OLEN + o_) * ODIM_ + n_] = acc[i][j] + bias[n_];
        }
    }
}

extern "C" void kernel_launch(void* const* d_in, const int* in_sizes, int n_in,
                              void* d_out, int out_size) {
    const float* hpad   = (const float*)d_in[0];
    const int*   ys     = (const int*)d_in[1];
    const float* w_enc  = (const float*)d_in[2];
    const float* b_enc  = (const float*)d_in[3];
    const float* w_dec  = (const float*)d_in[4];
    const float* w_att  = (const float*)d_in[5];
    const float* w_conv = (const float*)d_in[6];
    const float* w_gvec = (const float*)d_in[7];
    const float* embed  = (const float*)d_in[9];
    const float* w_ih   = (const float*)d_in[10];
    const float* w_hh   = (const float*)d_in[11];
    const float* b_ih   = (const float*)d_in[12];
    const float* b_hh   = (const float*)d_in[13];
    const float* w_out  = (const float*)d_in[14];
    const float* b_out  = (const float*)d_in[15];
    float* out = (float*)d_out;

    k_prep<<<8192, 256>>>(w_ih, w_hh, hpad, w_att);
    k_gemms<<<1832, 256>>>(hpad, w_enc, b_enc, w_ih, b_ih, b_hh, ys, embed);

    for (int step = 0; step < OLEN; step++) {
        k_small<<<384, 256>>>(w_dec, w_conv, step);
        k_e<<<dim3(50, BB), 128>>>(w_gvec);
        k_ctx<<<dim3(8, BB), 256>>>();
        k_lstm<<<256, 128>>>(step);
    }
    k_out<<<dim3(40, 26), 256>>>(w_out, b_out, out);
}

// round 13
// speedup vs baseline: 1.0767x; 1.0337x over previous
#include <cuda_runtime.h>
#include <cuda_fp16.h>

#define BB 32
#define TT 1000
#define EE 512
#define DD 1024
#define AA 512
#define CC 10
#define FF 100
#define KW 201
#define ODIM_ 5000
#define LL 100
#define OLEN 101
#define SOS_ 4998
#define NROW 4096
#define KCAT2 1536
#define MOUT 3232
#define MOUT_PAD 3328

__device__ __half g_preh[BB * TT * AA];          // 32.8 MB
__device__ __half g_hpadh[BB * TT * EE];         // 32.8 MB
__device__ __half g_wcat2h[NROW * KCAT2];        // 12.6 MB
__device__ float g_gey[MOUT_PAD * NROW];         // 54.5 MB (streamed)
__device__ __half2 g_wattp[10 * 256];
__device__ float g_aw[BB * TT];
__device__ float g_e[BB * TT];                   // exp(2e)
__device__ float g_epart[BB * 50];
__device__ float g_conv[BB * CC * TT];
__device__ float g_decp[4][BB * AA];
__device__ float g_ctxp2[2][BB * EE];
__device__ float g_z[2][BB * DD];
__device__ float g_c[BB * DD];
__device__ float g_zall[MOUT_PAD * DD];

__device__ __forceinline__ __half2 tanh2(__half2 x) {
    unsigned xi = *reinterpret_cast<unsigned*>(&x), yi;
    asm("tanh.approx.f16x2 %0, %1;" : "=r"(yi) : "r"(xi));
    return *reinterpret_cast<__half2*>(&yi);
}

// ---------- pre-loop kernel 1 ----------
__global__ void k_prep(const float* __restrict__ w_ih, const float* __restrict__ w_hh,
                       const float* __restrict__ hpad, const float* __restrict__ w_att) {
    const size_t TOT = 22742784;
    for (size_t i = (size_t)blockIdx.x * 256 + threadIdx.x; i < TOT; i += 2097152) {
        if (i < 32768) {
            g_z[0][i] = 0.f; g_c[i] = 0.f;
        } else if (i < 64768) {
            g_aw[i - 32768] = 1.0f / TT;
        } else if (i < 6356224) {
            int j = (int)(i - 64768);
            int r = j / KCAT2, k = j - r * KCAT2;
            int n = (r & 3) * DD + (r >> 2);
            float v = (k < EE) ? w_ih[(size_t)n * (DD + EE) + DD + k]
                               : w_hh[(size_t)n * DD + (k - EE)];
            g_wcat2h[j] = __float2half(v);
        } else if (i < 22740224) {
            size_t j = i - 6356224;
            g_hpadh[j] = __float2half(hpad[j]);
        } else {
            int j = (int)(i - 22740224);
            int c = j >> 8, p = j & 255;
            g_wattp[j] = __floats2half2_rn(w_att[(2 * p) * CC + c],
                                           w_att[(2 * p + 1) * CC + c]);
        }
    }
}

// ---------- pre-loop kernel 2: fused one-time GEMMs ----------
__global__ __launch_bounds__(256) void k_gemms(const float* __restrict__ hpad,
                                               const float* __restrict__ w_enc,
                                               const float* __restrict__ b_enc,
                                               const float* __restrict__ w_ih,
                                               const float* __restrict__ b_ih,
                                               const float* __restrict__ b_hh,
                                               const int* __restrict__ ys,
                                               const float* __restrict__ embed) {
    __shared__ float As[16][132];
    __shared__ float Bs[16][132];
    __shared__ int tok_s[128];
    int tid = threadIdx.x;
    bool is_pre = blockIdx.x >= 832;
    int m0, n0, K;
    if (is_pre) {
        int idx = blockIdx.x - 832;
        m0 = (idx >> 2) * 128; n0 = (idx & 3) * 128; K = 512;
    } else {
        m0 = ((int)blockIdx.x >> 5) * 128; n0 = ((int)blockIdx.x & 31) * 128; K = 1024;
        if (tid < 128) {
            int m = m0 + tid;
            int s = m >> 5, b = m & 31;
            tok_s[tid] = (s == 0 || s > 100) ? SOS_ : ys[b * LL + s - 1];
        }
        __syncthreads();
    }
    float acc[8][8];
#pragma unroll
    for (int i = 0; i < 8; i++)
#pragma unroll
        for (int j = 0; j < 8; j++) acc[i][j] = 0.f;
    int tm0 = (tid >> 4) << 3, tn0 = (tid & 15) << 3;
    for (int k0 = 0; k0 < K; k0 += 16) {
#pragma unroll
        for (int i = 0; i < 2; i++) {
            int lin = tid + (i << 8);
            int row = lin >> 2, kq = (lin & 3) << 2;
            float4 va, vb;
            if (is_pre) {
                va = *(const float4*)(hpad + (size_t)(m0 + row) * 512 + k0 + kq);
                vb = *(const float4*)(w_enc + (size_t)(n0 + row) * 512 + k0 + kq);
            } else {
                va = *(const float4*)(embed + (size_t)tok_s[row] * DD + k0 + kq);
                int r = n0 + row;
                int orig = (r & 3) * DD + (r >> 2);
                vb = *(const float4*)(w_ih + (size_t)orig * (DD + EE) + k0 + kq);
            }
            As[kq + 0][row] = va.x; As[kq + 1][row] = va.y;
            As[kq + 2][row] = va.z; As[kq + 3][row] = va.w;
            Bs[kq + 0][row] = vb.x; Bs[kq + 1][row] = vb.y;
            Bs[kq + 2][row] = vb.z; Bs[kq + 3][row] = vb.w;
        }
        __syncthreads();
#pragma unroll
        for (int kk = 0; kk < 16; kk++) {
            float a[8], b[8];
            *(float4*)&a[0] = *(const float4*)&As[kk][tm0];
            *(float4*)&a[4] = *(const float4*)&As[kk][tm0 + 4];
            *(float4*)&b[0] = *(const float4*)&Bs[kk][tn0];
            *(float4*)&b[4] = *(const float4*)&Bs[kk][tn0 + 4];
#pragma unroll
            for (int i = 0; i < 8; i++)
#pragma unroll
                for (int j = 0; j < 8; j++)
                    acc[i][j] = fmaf(a[i], b[j], acc[i][j]);
        }
        __syncthreads();
    }
#pragma unroll
    for (int i = 0; i < 8; i++) {
        int m_ = m0 + tm0 + i;
#pragma unroll
        for (int j = 0; j < 8; j++) {
            int n_ = n0 + tn0 + j;
            if (is_pre) {
                g_preh[(size_t)m_ * 512 + n_] = __float2half(acc[i][j] + b_enc[n_]);
            } else {
                int orig = (n_ & 3) * DD + (n_ >> 2);
                __stcs(&g_gey[(size_t)m_ * NROW + n_], acc[i][j] + b_ih[orig] + b_hh[orig]);
            }
        }
    }
}

// ---------- per-step: conv(aw) [0..319] + dec GEMM K-split [320..383] ----------
__global__ __launch_bounds__(256) void k_small(const float* __restrict__ w_dec,
                                               const float* __restrict__ w_conv, int step) {
    int blk = blockIdx.x, tid = threadIdx.x;
    if (blk < BB * CC) {
        __shared__ float sm[1408];
        int b = blk / CC, c = blk - b * CC;
        float* aw_s = sm;
        float* wk = sm + 1200;
        for (int i = tid; i < TT + 2 * FF; i += 256)
            aw_s[i] = (i >= FF && i < FF + TT) ? g_aw[b * TT + i - FF] : 0.f;
        for (int i = tid; i < KW; i += 256) wk[i] = w_conv[c * KW + i];
        __syncthreads();
        for (int t = tid; t < TT; t += 256) {
            float s = 0.f;
#pragma unroll 4
            for (int k = 0; k < KW; k++) s = fmaf(wk[k], aw_s[t + k], s);
            g_conv[(b * CC + c) * TT + t] = s;
        }
    } else {
        __shared__ float ws2[32][68];
        __shared__ float zs[64][36];
        int blk2 = blk - BB * CC;
        int ks = blk2 & 3, at = blk2 >> 2;
        int a0 = at * 32;
        int kbase = ks * 256;
        int zr = step & 1;
        int al = tid >> 3, bq = (tid & 7) << 2;
        int bbz = tid >> 3, kk0 = tid & 7;
        const float* zsrc = g_z[zr];
        float a0v = 0.f, a1v = 0.f, a2v = 0.f, a3v = 0.f;
        for (int kc = 0; kc < 4; kc++) {
            int k0 = kbase + kc * 64;
            __syncthreads();
#pragma unroll
            for (int i = 0; i < 2; i++) {
                int lin = tid + (i << 8);
                int row = lin >> 4, kq = (lin & 15) << 2;
                float4 w4 = *(const float4*)(w_dec + (size_t)(a0 + row) * DD + k0 + kq);
                ws2[row][kq + 0] = w4.x; ws2[row][kq + 1] = w4.y;
                ws2[row][kq + 2] = w4.z; ws2[row][kq + 3] = w4.w;
            }
#pragma unroll
            for (int j = 0; j < 8; j++) {
                int kk = kk0 + (j << 3);
                zs[kk][bbz] = zsrc[bbz * DD + k0 + kk];
            }
            __syncthreads();
#pragma unroll
            for (int kk = 0; kk < 64; kk++) {
                float w = ws2[al][kk];
                float4 x = *(const float4*)&zs[kk][bq];
                a0v = fmaf(w, x.x, a0v); a1v = fmaf(w, x.y, a1v);
                a2v = fmaf(w, x.z, a2v); a3v = fmaf(w, x.w, a3v);
            }
        }
        g_decp[ks][(bq + 0) * AA + a0 + al] = a0v;
        g_decp[ks][(bq + 1) * AA + a0 + al] = a1v;
        g_decp[ks][(bq + 2) * AA + a0 + al] = a2v;
        g_decp[ks][(bq + 3) * AA + a0 + al] = a3v;
    }
}

// ---------- per-step: exp(2*e[b,t]) half2 math, 10-deep load batches ----------
__global__ __launch_bounds__(128) void k_e(const float* __restrict__ w_gvec) {
    int b = blockIdx.y, t0 = blockIdx.x * 20;
    int tid = threadIdx.x;
    __shared__ __half2 conv_s2[20][10];
    __shared__ float part_s[20][4];
    __shared__ float exps[20];
    for (int i = tid; i < 200; i += 128) {
        int c = i / 20, tl = i - c * 20;
        conv_s2[tl][c] = __float2half2_rn(g_conv[(b * CC + c) * TT + t0 + tl]);
    }
    int a0 = tid * 4, p0 = tid * 2;
    __half2 wr2[2][10];
    float gg[4], dcf[4];
#pragma unroll
    for (int pp = 0; pp < 2; pp++)
#pragma unroll
        for (int c = 0; c < 10; c++) wr2[pp][c] = g_wattp[(c << 8) + p0 + pp];
#pragma unroll
    for (int j = 0; j < 4; j++) {
        gg[j] = w_gvec[a0 + j];
        int ai = b * AA + a0 + j;
        dcf[j] = g_decp[0][ai] + g_decp[1][ai] + g_decp[2][ai] + g_decp[3][ai];
    }
    __half2 dch0 = __floats2half2_rn(dcf[0], dcf[1]);
    __half2 dch1 = __floats2half2_rn(dcf[2], dcf[3]);
    __syncthreads();
    int lane = tid & 31, warp = tid >> 5;
    const __half2* prep = (const __half2*)(g_preh + ((size_t)b * TT + t0) * AA + a0);
    for (int tq = 0; tq < 20; tq += 10) {
        uint2 u[10];
#pragma unroll
        for (int q = 0; q < 10; q++)
            u[q] = *(const uint2*)(prep + (size_t)(tq + q) * (AA / 2));
        float acc[10];
#pragma unroll
        for (int q = 0; q < 10; q++) {
            __half2 pa0 = *reinterpret_cast<__half2*>(&u[q].x);
            __half2 pa1 = *reinterpret_cast<__half2*>(&u[q].y);
            __half2 x0 = __hadd2(pa0, dch0);
            __half2 x1 = __hadd2(pa1, dch1);
#pragma unroll
            for (int c = 0; c < 10; c++) {
                __half2 cvt = conv_s2[tq + q][c];
                x0 = __hfma2(cvt, wr2[0][c], x0);
                x1 = __hfma2(cvt, wr2[1][c], x1);
            }
            float2 f0 = __half22float2(tanh2(x0));
            float2 f1 = __half22float2(tanh2(x1));
            acc[q] = gg[0] * f0.x + gg[1] * f0.y + gg[2] * f1.x + gg[3] * f1.y;
        }
#pragma unroll
        for (int s = 16; s; s >>= 1) {
#pragma unroll
            for (int q = 0; q < 10; q++)
                acc[q] += __shfl_xor_sync(0xffffffffu, acc[q], s);
        }
        if (lane == 0) {
#pragma unroll
            for (int q = 0; q < 10; q++) part_s[tq + q][warp] = acc[q];
        }
    }
    __syncthreads();
    if (tid < 20) {
        float e = part_s[tid][0] + part_s[tid][1] + part_s[tid][2] + part_s[tid][3];
        float ex = __expf(2.f * e);          // no-max softmax: |e| <= ~8, safe
        g_e[b * TT + t0 + tid] = ex;
        exps[tid] = ex;
    }
    __syncthreads();
    if (tid == 0) {
        float s = 0.f;
#pragma unroll
        for (int i = 0; i < 20; i++) s += exps[i];
        g_epart[b * 50 + blockIdx.x] = s;
    }
}

// ---------- per-step: normalize + ctx partials (T-split 2, half2 ldcs) + aw ----------
__global__ __launch_bounds__(256) void k_ctx() {
    int b = blockIdx.y;
    int ec = blockIdx.x & 3, tc = blockIdx.x >> 2;
    int tid = threadIdx.x;
    __shared__ float wsm[500];
    __shared__ float sred[64];
    __shared__ float2 red2[256];
    if (tid < 64) sred[tid] = (tid < 50) ? g_epart[b * 50 + tid] : 0.f;
    __syncthreads();
    if (tid < 32) {
        float v = sred[tid] + sred[tid + 32];
#pragma unroll
        for (int s = 16; s; s >>= 1) v += __shfl_xor_sync(0xffffffffu, v, s);
        if (tid == 0) sred[0] = v;
    }
    __syncthreads();
    float inv = 1.f / sred[0];
    int tbase = tc * 500;
    for (int i = tid; i < 500; i += 256) {
        float w = g_e[b * TT + tbase + i] * inv;
        wsm[i] = w;
        if (ec == 0) g_aw[b * TT + tbase + i] = w;
    }
    __syncthreads();
    int el2 = (tid & 63) * 2, h = tid >> 6;   // 4 sub-chunks of 125
    int e0 = ec * 128;
    const __half2* hp =
        (const __half2*)(g_hpadh + ((size_t)b * TT + tbase + h * 125) * EE + e0 + el2);
    const float* wp = wsm + h * 125;
    float ax = 0.f, ay = 0.f;
#pragma unroll 5
    for (int i = 0; i < 125; i++) {
        __half2 hv = __ldcs(hp + (size_t)i * 256);
        float2 f = __half22float2(hv);
        float w = wp[i];
        ax = fmaf(w, f.x, ax); ay = fmaf(w, f.y, ay);
    }
    red2[tid] = make_float2(ax, ay);
    __syncthreads();
    if (tid < 64) {
        float2 s0 = red2[tid], s1 = red2[tid + 64];
        float2 s2 = red2[tid + 128], s3 = red2[tid + 192];
        g_ctxp2[tc][b * EE + e0 + tid * 2 + 0] = s0.x + s1.x + s2.x + s3.x;
        g_ctxp2[tc][b * EE + e0 + tid * 2 + 1] = s0.y + s1.y + s2.y + s3.y;
    }
}

// ---------- per-step: LSTM gates (fp16 weights, r-tile 16, 256 blocks) + cell ----------
__global__ __launch_bounds__(128) void k_lstm(int step) {
    __shared__ float ws[16][68];
    __shared__ float xs[64][36];
    __shared__ float gates_s[16][33];
    int tid = threadIdx.x;
    int r0 = blockIdx.x * 16;
    int zr = step & 1;
    int rl = tid >> 3, b0 = (tid & 7) << 2;
    int bb = tid >> 2, kk0 = tid & 3;
    float acc0 = __ldcs(&g_gey[(size_t)(step * BB + b0 + 0) * NROW + r0 + rl]);
    float acc1 = __ldcs(&g_gey[(size_t)(step * BB + b0 + 1) * NROW + r0 + rl]);
    float acc2 = __ldcs(&g_gey[(size_t)(step * BB + b0 + 2) * NROW + r0 + rl]);
    float acc3 = __ldcs(&g_gey[(size_t)(step * BB + b0 + 3) * NROW + r0 + rl]);
    const float* zsrc = g_z[zr];
    int wrow = tid >> 3, wkq = (tid & 7) << 3;
    for (int k0 = 0; k0 < KCAT2; k0 += 64) {
        {
            uint4 w8 = *(const uint4*)(g_wcat2h + (size_t)(r0 + wrow) * KCAT2 + k0 + wkq);
            __half2* hp = (__half2*)&w8;
            float2 f0 = __half22float2(hp[0]);
            float2 f1 = __half22float2(hp[1]);
            float2 f2 = __half22float2(hp[2]);
            float2 f3 = __half22float2(hp[3]);
            ws[wrow][wkq + 0] = f0.x; ws[wrow][wkq + 1] = f0.y;
            ws[wrow][wkq + 2] = f1.x; ws[wrow][wkq + 3] = f1.y;
            ws[wrow][wkq + 4] = f2.x; ws[wrow][wkq + 5] = f2.y;
            ws[wrow][wkq + 6] = f3.x; ws[wrow][wkq + 7] = f3.y;
        }
#pragma unroll
        for (int j = 0; j < 16; j++) {
            int kk = kk0 + (j << 2);
            int k = k0 + kk;
            float v;
            if (k < EE) {
                int ci = bb * EE + k;
                v = g_ctxp2[0][ci] + g_ctxp2[1][ci];
            } else v = zsrc[bb * DD + (k - EE)];
            xs[kk][bb] = v;
        }
        __syncthreads();
#pragma unroll
        for (int kk = 0; kk < 64; kk++) {
            float w = ws[rl][kk];
            float4 x = *(const float4*)&xs[kk][b0];
            acc0 = fmaf(w, x.x, acc0); acc1 = fmaf(w, x.y, acc1);
            acc2 = fmaf(w, x.z, acc2); acc3 = fmaf(w, x.w, acc3);
        }
        __syncthreads();
    }
    gates_s[rl][b0 + 0] = acc0;
    gates_s[rl][b0 + 1] = acc1;
    gates_s[rl][b0 + 2] = acc2;
    gates_s[rl][b0 + 3] = acc3;
    __syncthreads();
    int dl = tid >> 5, b = tid & 31;
    int d = (r0 >> 2) + dl;
    float iv = gates_s[dl * 4 + 0][b];
    float fv = gates_s[dl * 4 + 1][b];
    float gv = gates_s[dl * 4 + 2][b];
    float ov = gates_s[dl * 4 + 3][b];
    float si = 1.f / (1.f + expf(-iv));
    float sf = 1.f / (1.f + expf(-fv));
    float so = 1.f / (1.f + expf(-ov));
    float cn = sf * g_c[b * DD + d] + si * tanhf(gv);
    float zn = so * tanhf(cn);
    g_c[b * DD + d] = cn;
    g_z[zr ^ 1][b * DD + d] = zn;
    __stcs(&g_zall[(size_t)(step * BB + b) * DD + d], zn);
}

// ---------- final: out = z_all @ w_out^T + b_out ----------
__global__ __launch_bounds__(256) void k_out(const float* __restrict__ Bm,
                                             const float* __restrict__ bias,
                                             float* __restrict__ Cout) {
    __shared__ float As[16][132];
    __shared__ float Bs[16][132];
    int tid = threadIdx.x;
    int m0 = blockIdx.y * 128, n0 = blockIdx.x * 128;
    float acc[8][8];
#pragma unroll
    for (int i = 0; i < 8; i++)
#pragma unroll
        for (int j = 0; j < 8; j++) acc[i][j] = 0.f;
    int tm0 = (tid >> 4) << 3, tn0 = (tid & 15) << 3;
    for (int k0 = 0; k0 < DD; k0 += 16) {
#pragma unroll
        for (int i = 0; i < 2; i++) {
            int lin = tid + (i << 8);
            int row = lin >> 2, kq = (lin & 3) << 2;
            float4 va = *(const float4*)(g_zall + (size_t)(m0 + row) * DD + k0 + kq);
            As[kq + 0][row] = va.x; As[kq + 1][row] = va.y;
            As[kq + 2][row] = va.z; As[kq + 3][row] = va.w;
            int nr = n0 + row;
            float4 vb = make_float4(0.f, 0.f, 0.f, 0.f);
            if (nr < ODIM_) vb = *(const float4*)(Bm + (size_t)nr * DD + k0 + kq);
            Bs[kq + 0][row] = vb.x; Bs[kq + 1][row] = vb.y;
            Bs[kq + 2][row] = vb.z; Bs[kq + 3][row] = vb.w;
        }
        __syncthreads();
#pragma unroll
        for (int kk = 0; kk < 16; kk++) {
            float a[8], b[8];
            *(float4*)&a[0] = *(const float4*)&As[kk][tm0];
            *(float4*)&a[4] = *(const float4*)&As[kk][tm0 + 4];
            *(float4*)&b[0] = *(const float4*)&Bs[kk][tn0];
            *(float4*)&b[4] = *(const float4*)&Bs[kk][tn0 + 4];
#pragma unroll
            for (int i = 0; i < 8; i++)
#pragma unroll
                for (int j = 0; j < 8; j++)
                    acc[i][j] = fmaf(a[i], b[j], acc[i][j]);
        }
        __syncthreads();
    }
#pragma unroll
    for (int i = 0; i < 8; i++) {
        int m_ = m0 + tm0 + i;
        if (m_ >= MOUT) continue;
        int b_ = m_ & 31, o_ = m_ >> 5;
#pragma unroll
        for (int j = 0; j < 8; j++) {
            int n_ = n0 + tn0 + j;
            if (n_ >= ODIM_) continue;
            Cout[(size_t)(b_ * OLEN + o_) * ODIM_ + n_] = acc[i][j] + bias[n_];
        }
    }
}

extern "C" void kernel_launch(void* const* d_in, const int* in_sizes, int n_in,
                              void* d_out, int out_size) {
    const float* hpad   = (const float*)d_in[0];
    const int*   ys     = (const int*)d_in[1];
    const float* w_enc  = (const float*)d_in[2];
    const float* b_enc  = (const float*)d_in[3];
    const float* w_dec  = (const float*)d_in[4];
    const float* w_att  = (const float*)d_in[5];
    const float* w_conv = (const float*)d_in[6];
    const float* w_gvec = (const float*)d_in[7];
    const float* embed  = (const float*)d_in[9];
    const float* w_ih   = (const float*)d_in[10];
    const float* w_hh   = (const float*)d_in[11];
    const float* b_ih   = (const float*)d_in[12];
    const float* b_hh   = (const float*)d_in[13];
    const float* w_out  = (const float*)d_in[14];
    const float* b_out  = (const float*)d_in[15];
    float* out = (float*)d_out;

    k_prep<<<8192, 256>>>(w_ih, w_hh, hpad, w_att);
    k_gemms<<<1832, 256>>>(hpad, w_enc, b_enc, w_ih, b_ih, b_hh, ys, embed);

    for (int step = 0; step < OLEN; step++) {
        k_small<<<384, 256>>>(w_dec, w_conv, step);
        k_e<<<dim3(50, BB), 128>>>(w_gvec);
        k_ctx<<<dim3(8, BB), 256>>>();
        k_lstm<<<256, 128>>>(step);
    }
    k_out<<<dim3(40, 26), 256>>>(w_out, b_out, out);
}

// round 14
// speedup vs baseline: 1.1914x; 1.1066x over previous
#include <cuda_runtime.h>
#include <cuda_fp16.h>

#define BB 32
#define TT 1000
#define EE 512
#define DD 1024
#define AA 512
#define CC 10
#define FF 100
#define KW 201
#define ODIM_ 5000
#define LL 100
#define OLEN 101
#define SOS_ 4998
#define NROW 4096
#define KCAT2 1536
#define MOUT 3232
#define MOUT_PAD 3328

__device__ __half g_preh[BB * TT * AA];          // 32.8 MB
__device__ __half g_hpadh[BB * TT * EE];         // 32.8 MB
__device__ __half g_wcat2h[NROW * KCAT2];        // 12.6 MB
__device__ float g_gey[MOUT_PAD * NROW];         // 54.5 MB (streamed)
__device__ __half2 g_wattp[10 * 256];
__device__ float g_aw[BB * TT];
__device__ float g_e[BB * TT];                   // exp(2e)
__device__ float g_epart[BB * 50];
__device__ float g_conv[BB * CC * TT];
__device__ float g_decp[4][BB * AA];
__device__ float g_ctxp2[2][BB * EE];
__device__ float g_z[2][BB * DD];
__device__ float g_c[BB * DD];
__device__ float g_zall[MOUT_PAD * DD];

__device__ __forceinline__ __half2 tanh2(__half2 x) {
    unsigned xi = *reinterpret_cast<unsigned*>(&x), yi;
    asm("tanh.approx.f16x2 %0, %1;" : "=r"(yi) : "r"(xi));
    return *reinterpret_cast<__half2*>(&yi);
}

// ---------- pre-loop kernel 1 ----------
__global__ void k_prep(const float* __restrict__ w_ih, const float* __restrict__ w_hh,
                       const float* __restrict__ hpad, const float* __restrict__ w_att) {
    const size_t TOT = 22742784;
    for (size_t i = (size_t)blockIdx.x * 256 + threadIdx.x; i < TOT; i += 2097152) {
        if (i < 32768) {
            g_z[0][i] = 0.f; g_c[i] = 0.f;
        } else if (i < 64768) {
            g_aw[i - 32768] = 1.0f / TT;
        } else if (i < 6356224) {
            int j = (int)(i - 64768);
            int r = j / KCAT2, k = j - r * KCAT2;
            int n = (r & 3) * DD + (r >> 2);
            float v = (k < EE) ? w_ih[(size_t)n * (DD + EE) + DD + k]
                               : w_hh[(size_t)n * DD + (k - EE)];
            g_wcat2h[j] = __float2half(v);
        } else if (i < 22740224) {
            size_t j = i - 6356224;
            g_hpadh[j] = __float2half(hpad[j]);
        } else {
            int j = (int)(i - 22740224);
            int c = j >> 8, p = j & 255;
            g_wattp[j] = __floats2half2_rn(w_att[(2 * p) * CC + c],
                                           w_att[(2 * p + 1) * CC + c]);
        }
    }
}

// ---------- pre-loop kernel 2: fused one-time GEMMs ----------
__global__ __launch_bounds__(256) void k_gemms(const float* __restrict__ hpad,
                                               const float* __restrict__ w_enc,
                                               const float* __restrict__ b_enc,
                                               const float* __restrict__ w_ih,
                                               const float* __restrict__ b_ih,
                                               const float* __restrict__ b_hh,
                                               const int* __restrict__ ys,
                                               const float* __restrict__ embed) {
    __shared__ float As[16][132];
    __shared__ float Bs[16][132];
    __shared__ int tok_s[128];
    int tid = threadIdx.x;
    bool is_pre = blockIdx.x >= 832;
    int m0, n0, K;
    if (is_pre) {
        int idx = blockIdx.x - 832;
        m0 = (idx >> 2) * 128; n0 = (idx & 3) * 128; K = 512;
    } else {
        m0 = ((int)blockIdx.x >> 5) * 128; n0 = ((int)blockIdx.x & 31) * 128; K = 1024;
        if (tid < 128) {
            int m = m0 + tid;
            int s = m >> 5, b = m & 31;
            tok_s[tid] = (s == 0 || s > 100) ? SOS_ : ys[b * LL + s - 1];
        }
        __syncthreads();
    }
    float acc[8][8];
#pragma unroll
    for (int i = 0; i < 8; i++)
#pragma unroll
        for (int j = 0; j < 8; j++) acc[i][j] = 0.f;
    int tm0 = (tid >> 4) << 3, tn0 = (tid & 15) << 3;
    for (int k0 = 0; k0 < K; k0 += 16) {
#pragma unroll
        for (int i = 0; i < 2; i++) {
            int lin = tid + (i << 8);
            int row = lin >> 2, kq = (lin & 3) << 2;
            float4 va, vb;
            if (is_pre) {
                va = *(const float4*)(hpad + (size_t)(m0 + row) * 512 + k0 + kq);
                vb = *(const float4*)(w_enc + (size_t)(n0 + row) * 512 + k0 + kq);
            } else {
                va = *(const float4*)(embed + (size_t)tok_s[row] * DD + k0 + kq);
                int r = n0 + row;
                int orig = (r & 3) * DD + (r >> 2);
                vb = *(const float4*)(w_ih + (size_t)orig * (DD + EE) + k0 + kq);
            }
            As[kq + 0][row] = va.x; As[kq + 1][row] = va.y;
            As[kq + 2][row] = va.z; As[kq + 3][row] = va.w;
            Bs[kq + 0][row] = vb.x; Bs[kq + 1][row] = vb.y;
            Bs[kq + 2][row] = vb.z; Bs[kq + 3][row] = vb.w;
        }
        __syncthreads();
#pragma unroll
        for (int kk = 0; kk < 16; kk++) {
            float a[8], b[8];
            *(float4*)&a[0] = *(const float4*)&As[kk][tm0];
            *(float4*)&a[4] = *(const float4*)&As[kk][tm0 + 4];
            *(float4*)&b[0] = *(const float4*)&Bs[kk][tn0];
            *(float4*)&b[4] = *(const float4*)&Bs[kk][tn0 + 4];
#pragma unroll
            for (int i = 0; i < 8; i++)
#pragma unroll
                for (int j = 0; j < 8; j++)
                    acc[i][j] = fmaf(a[i], b[j], acc[i][j]);
        }
        __syncthreads();
    }
#pragma unroll
    for (int i = 0; i < 8; i++) {
        int m_ = m0 + tm0 + i;
#pragma unroll
        for (int j = 0; j < 8; j++) {
            int n_ = n0 + tn0 + j;
            if (is_pre) {
                g_preh[(size_t)m_ * 512 + n_] = __float2half(acc[i][j] + b_enc[n_]);
            } else {
                int orig = (n_ & 3) * DD + (n_ >> 2);
                __stcs(&g_gey[(size_t)m_ * NROW + n_], acc[i][j] + b_ih[orig] + b_hh[orig]);
            }
        }
    }
}

// ---------- per-step: conv(aw) [0..319] + dec GEMM K-split [320..383] ----------
__global__ __launch_bounds__(256) void k_small(const float* __restrict__ w_dec,
                                               const float* __restrict__ w_conv, int step) {
    int blk = blockIdx.x, tid = threadIdx.x;
    if (blk < BB * CC) {
        __shared__ float sm[1408];
        int b = blk / CC, c = blk - b * CC;
        float* aw_s = sm;
        float* wk = sm + 1200;
        for (int i = tid; i < TT + 2 * FF; i += 256)
            aw_s[i] = (i >= FF && i < FF + TT) ? g_aw[b * TT + i - FF] : 0.f;
        for (int i = tid; i < KW; i += 256) wk[i] = w_conv[c * KW + i];
        __syncthreads();
        for (int t = tid; t < TT; t += 256) {
            float s = 0.f;
#pragma unroll 4
            for (int k = 0; k < KW; k++) s = fmaf(wk[k], aw_s[t + k], s);
            g_conv[(b * CC + c) * TT + t] = s;
        }
    } else {
        __shared__ float ws2[32][68];
        __shared__ float zs[64][36];
        int blk2 = blk - BB * CC;
        int ks = blk2 & 3, at = blk2 >> 2;
        int a0 = at * 32;
        int kbase = ks * 256;
        int zr = step & 1;
        int al = tid >> 3, bq = (tid & 7) << 2;
        int bbz = tid >> 3, kk0 = tid & 7;
        const float* zsrc = g_z[zr];
        float a0v = 0.f, a1v = 0.f, a2v = 0.f, a3v = 0.f;
        for (int kc = 0; kc < 4; kc++) {
            int k0 = kbase + kc * 64;
            __syncthreads();
#pragma unroll
            for (int i = 0; i < 2; i++) {
                int lin = tid + (i << 8);
                int row = lin >> 4, kq = (lin & 15) << 2;
                float4 w4 = *(const float4*)(w_dec + (size_t)(a0 + row) * DD + k0 + kq);
                ws2[row][kq + 0] = w4.x; ws2[row][kq + 1] = w4.y;
                ws2[row][kq + 2] = w4.z; ws2[row][kq + 3] = w4.w;
            }
#pragma unroll
            for (int j = 0; j < 8; j++) {
                int kk = kk0 + (j << 3);
                zs[kk][bbz] = zsrc[bbz * DD + k0 + kk];
            }
            __syncthreads();
#pragma unroll
            for (int kk = 0; kk < 64; kk++) {
                float w = ws2[al][kk];
                float4 x = *(const float4*)&zs[kk][bq];
                a0v = fmaf(w, x.x, a0v); a1v = fmaf(w, x.y, a1v);
                a2v = fmaf(w, x.z, a2v); a3v = fmaf(w, x.w, a3v);
            }
        }
        g_decp[ks][(bq + 0) * AA + a0 + al] = a0v;
        g_decp[ks][(bq + 1) * AA + a0 + al] = a1v;
        g_decp[ks][(bq + 2) * AA + a0 + al] = a2v;
        g_decp[ks][(bq + 3) * AA + a0 + al] = a3v;
    }
}

// ---------- per-step: exp(2*e[b,t]) half2 math, 10-deep load batches ----------
__global__ __launch_bounds__(128) void k_e(const float* __restrict__ w_gvec) {
    int b = blockIdx.y, t0 = blockIdx.x * 20;
    int tid = threadIdx.x;
    __shared__ __half2 conv_s2[20][10];
    __shared__ float part_s[20][4];
    __shared__ float exps[20];
    for (int i = tid; i < 200; i += 128) {
        int c = i / 20, tl = i - c * 20;
        conv_s2[tl][c] = __float2half2_rn(g_conv[(b * CC + c) * TT + t0 + tl]);
    }
    int a0 = tid * 4, p0 = tid * 2;
    __half2 wr2[2][10];
    float gg[4], dcf[4];
#pragma unroll
    for (int pp = 0; pp < 2; pp++)
#pragma unroll
        for (int c = 0; c < 10; c++) wr2[pp][c] = g_wattp[(c << 8) + p0 + pp];
#pragma unroll
    for (int j = 0; j < 4; j++) {
        gg[j] = w_gvec[a0 + j];
        int ai = b * AA + a0 + j;
        dcf[j] = g_decp[0][ai] + g_decp[1][ai] + g_decp[2][ai] + g_decp[3][ai];
    }
    __half2 dch0 = __floats2half2_rn(dcf[0], dcf[1]);
    __half2 dch1 = __floats2half2_rn(dcf[2], dcf[3]);
    __syncthreads();
    int lane = tid & 31, warp = tid >> 5;
    const __half2* prep = (const __half2*)(g_preh + ((size_t)b * TT + t0) * AA + a0);
    for (int tq = 0; tq < 20; tq += 10) {
        uint2 u[10];
#pragma unroll
        for (int q = 0; q < 10; q++)
            u[q] = *(const uint2*)(prep + (size_t)(tq + q) * (AA / 2));
        float acc[10];
#pragma unroll
        for (int q = 0; q < 10; q++) {
            __half2 pa0 = *reinterpret_cast<__half2*>(&u[q].x);
            __half2 pa1 = *reinterpret_cast<__half2*>(&u[q].y);
            __half2 x0 = __hadd2(pa0, dch0);
            __half2 x1 = __hadd2(pa1, dch1);
#pragma unroll
            for (int c = 0; c < 10; c++) {
                __half2 cvt = conv_s2[tq + q][c];
                x0 = __hfma2(cvt, wr2[0][c], x0);
                x1 = __hfma2(cvt, wr2[1][c], x1);
            }
            float2 f0 = __half22float2(tanh2(x0));
            float2 f1 = __half22float2(tanh2(x1));
            acc[q] = gg[0] * f0.x + gg[1] * f0.y + gg[2] * f1.x + gg[3] * f1.y;
        }
#pragma unroll
        for (int s = 16; s; s >>= 1) {
#pragma unroll
            for (int q = 0; q < 10; q++)
                acc[q] += __shfl_xor_sync(0xffffffffu, acc[q], s);
        }
        if (lane == 0) {
#pragma unroll
            for (int q = 0; q < 10; q++) part_s[tq + q][warp] = acc[q];
        }
    }
    __syncthreads();
    if (tid < 20) {
        float e = part_s[tid][0] + part_s[tid][1] + part_s[tid][2] + part_s[tid][3];
        float ex = __expf(2.f * e);          // no-max softmax: |e| <= ~8, safe
        g_e[b * TT + t0 + tid] = ex;
        exps[tid] = ex;
    }
    __syncthreads();
    if (tid == 0) {
        float s = 0.f;
#pragma unroll
        for (int i = 0; i < 20; i++) s += exps[i];
        g_epart[b * 50 + blockIdx.x] = s;
    }
}

// ---------- per-step: normalize + ctx partials (25-deep half2 ldcs batches) + aw ----------
__global__ __launch_bounds__(256) void k_ctx() {
    int b = blockIdx.y;
    int ec = blockIdx.x & 3, tc = blockIdx.x >> 2;
    int tid = threadIdx.x;
    __shared__ float wsm[500];
    __shared__ float sred[64];
    __shared__ float2 red2[256];
    if (tid < 64) sred[tid] = (tid < 50) ? g_epart[b * 50 + tid] : 0.f;
    __syncthreads();
    if (tid < 32) {
        float v = sred[tid] + sred[tid + 32];
#pragma unroll
        for (int s = 16; s; s >>= 1) v += __shfl_xor_sync(0xffffffffu, v, s);
        if (tid == 0) sred[0] = v;
    }
    __syncthreads();
    float inv = 1.f / sred[0];
    int tbase = tc * 500;
    for (int i = tid; i < 500; i += 256) {
        float w = g_e[b * TT + tbase + i] * inv;
        wsm[i] = w;
        if (ec == 0) g_aw[b * TT + tbase + i] = w;
    }
    __syncthreads();
    int el2 = (tid & 63) * 2, h = tid >> 6;   // 4 sub-chunks of 125
    int e0 = ec * 128;
    const __half2* hp =
        (const __half2*)(g_hpadh + ((size_t)b * TT + tbase + h * 125) * EE + e0 + el2);
    const float* wp = wsm + h * 125;
    float ax = 0.f, ay = 0.f;
    for (int i0 = 0; i0 < 125; i0 += 25) {
        __half2 hv[25];
#pragma unroll
        for (int q = 0; q < 25; q++)
            hv[q] = __ldcs(hp + (size_t)(i0 + q) * 256);
#pragma unroll
        for (int q = 0; q < 25; q++) {
            float2 f = __half22float2(hv[q]);
            float w = wp[i0 + q];
            ax = fmaf(w, f.x, ax); ay = fmaf(w, f.y, ay);
        }
    }
    red2[tid] = make_float2(ax, ay);
    __syncthreads();
    if (tid < 64) {
        float2 s0 = red2[tid], s1 = red2[tid + 64];
        float2 s2 = red2[tid + 128], s3 = red2[tid + 192];
        g_ctxp2[tc][b * EE + e0 + tid * 2 + 0] = s0.x + s1.x + s2.x + s3.x;
        g_ctxp2[tc][b * EE + e0 + tid * 2 + 1] = s0.y + s1.y + s2.y + s3.y;
    }
}

// ---------- per-step: LSTM gates, double-buffered smem pipeline + cell ----------
__global__ __launch_bounds__(128) void k_lstm(int step) {
    __shared__ float ws[2][16][68];
    __shared__ float xs[2][64][36];
    __shared__ float gates_s[16][33];
    int tid = threadIdx.x;
    int r0 = blockIdx.x * 16;
    int zr = step & 1;
    int rl = tid >> 3, b0 = (tid & 7) << 2;
    int bb = tid >> 2, kk0 = tid & 3;
    float acc0 = __ldcs(&g_gey[(size_t)(step * BB + b0 + 0) * NROW + r0 + rl]);
    float acc1 = __ldcs(&g_gey[(size_t)(step * BB + b0 + 1) * NROW + r0 + rl]);
    float acc2 = __ldcs(&g_gey[(size_t)(step * BB + b0 + 2) * NROW + r0 + rl]);
    float acc3 = __ldcs(&g_gey[(size_t)(step * BB + b0 + 3) * NROW + r0 + rl]);
    const float* zsrc = g_z[zr];
    int wrow = tid >> 3, wkq = (tid & 7) << 3;

    uint4 w8;
    float xv[16];
    // prefetch chunk 0
    w8 = *(const uint4*)(g_wcat2h + (size_t)(r0 + wrow) * KCAT2 + wkq);
#pragma unroll
    for (int j = 0; j < 16; j++) {
        int k = kk0 + (j << 2);
        xv[j] = (k < EE) ? (g_ctxp2[0][bb * EE + k] + g_ctxp2[1][bb * EE + k])
                         : zsrc[bb * DD + (k - EE)];
    }
    for (int c = 0; c < 24; c++) {
        int p = c & 1;
        // stage prefetched data
        {
            __half2* hp = (__half2*)&w8;
            float2 f0 = __half22float2(hp[0]);
            float2 f1 = __half22float2(hp[1]);
            float2 f2 = __half22float2(hp[2]);
            float2 f3 = __half22float2(hp[3]);
            ws[p][wrow][wkq + 0] = f0.x; ws[p][wrow][wkq + 1] = f0.y;
            ws[p][wrow][wkq + 2] = f1.x; ws[p][wrow][wkq + 3] = f1.y;
            ws[p][wrow][wkq + 4] = f2.x; ws[p][wrow][wkq + 5] = f2.y;
            ws[p][wrow][wkq + 6] = f3.x; ws[p][wrow][wkq + 7] = f3.y;
        }
#pragma unroll
        for (int j = 0; j < 16; j++) xs[p][kk0 + (j << 2)][bb] = xv[j];
        __syncthreads();
        // prefetch next chunk (global loads overlap compute below)
        if (c < 23) {
            int k0 = (c + 1) * 64;
            w8 = *(const uint4*)(g_wcat2h + (size_t)(r0 + wrow) * KCAT2 + k0 + wkq);
#pragma unroll
            for (int j = 0; j < 16; j++) {
                int k = k0 + kk0 + (j << 2);
                xv[j] = (k < EE) ? (g_ctxp2[0][bb * EE + k] + g_ctxp2[1][bb * EE + k])
                                 : zsrc[bb * DD + (k - EE)];
            }
        }
        // compute chunk c
#pragma unroll
        for (int kk = 0; kk < 64; kk++) {
            float w = ws[p][rl][kk];
            float4 x = *(const float4*)&xs[p][kk][b0];
            acc0 = fmaf(w, x.x, acc0); acc1 = fmaf(w, x.y, acc1);
            acc2 = fmaf(w, x.z, acc2); acc3 = fmaf(w, x.w, acc3);
        }
    }
    __syncthreads();
    gates_s[rl][b0 + 0] = acc0;
    gates_s[rl][b0 + 1] = acc1;
    gates_s[rl][b0 + 2] = acc2;
    gates_s[rl][b0 + 3] = acc3;
    __syncthreads();
    int dl = tid >> 5, b = tid & 31;
    int d = (r0 >> 2) + dl;
    float iv = gates_s[dl * 4 + 0][b];
    float fv = gates_s[dl * 4 + 1][b];
    float gv = gates_s[dl * 4 + 2][b];
    float ov = gates_s[dl * 4 + 3][b];
    float si = 1.f / (1.f + expf(-iv));
    float sf = 1.f / (1.f + expf(-fv));
    float so = 1.f / (1.f + expf(-ov));
    float cn = sf * g_c[b * DD + d] + si * tanhf(gv);
    float zn = so * tanhf(cn);
    g_c[b * DD + d] = cn;
    g_z[zr ^ 1][b * DD + d] = zn;
    __stcs(&g_zall[(size_t)(step * BB + b) * DD + d], zn);
}

// ---------- final: out = z_all @ w_out^T + b_out ----------
__global__ __launch_bounds__(256) void k_out(const float* __restrict__ Bm,
                                             const float* __restrict__ bias,
                                             float* __restrict__ Cout) {
    __shared__ float As[16][132];
    __shared__ float Bs[16][132];
    int tid = threadIdx.x;
    int m0 = blockIdx.y * 128, n0 = blockIdx.x * 128;
    float acc[8][8];
#pragma unroll
    for (int i = 0; i < 8; i++)
#pragma unroll
        for (int j = 0; j < 8; j++) acc[i][j] = 0.f;
    int tm0 = (tid >> 4) << 3, tn0 = (tid & 15) << 3;
    for (int k0 = 0; k0 < DD; k0 += 16) {
#pragma unroll
        for (int i = 0; i < 2; i++) {
            int lin = tid + (i << 8);
            int row = lin >> 2, kq = (lin & 3) << 2;
            float4 va = *(const float4*)(g_zall + (size_t)(m0 + row) * DD + k0 + kq);
            As[kq + 0][row] = va.x; As[kq + 1][row] = va.y;
            As[kq + 2][row] = va.z; As[kq + 3][row] = va.w;
            int nr = n0 + row;
            float4 vb = make_float4(0.f, 0.f, 0.f, 0.f);
            if (nr < ODIM_) vb = *(const float4*)(Bm + (size_t)nr * DD + k0 + kq);
            Bs[kq + 0][row] = vb.x; Bs[kq + 1][row] = vb.y;
            Bs[kq + 2][row] = vb.z; Bs[kq + 3][row] = vb.w;
        }
        __syncthreads();
#pragma unroll
        for (int kk = 0; kk < 16; kk++) {
            float a[8], b[8];
            *(float4*)&a[0] = *(const float4*)&As[kk][tm0];
            *(float4*)&a[4] = *(const float4*)&As[kk][tm0 + 4];
            *(float4*)&b[0] = *(const float4*)&Bs[kk][tn0];
            *(float4*)&b[4] = *(const float4*)&Bs[kk][tn0 + 4];
#pragma unroll
            for (int i = 0; i < 8; i++)
#pragma unroll
                for (int j = 0; j < 8; j++)
                    acc[i][j] = fmaf(a[i], b[j], acc[i][j]);
        }
        __syncthreads();
    }
#pragma unroll
    for (int i = 0; i < 8; i++) {
        int m_ = m0 + tm0 + i;
        if (m_ >= MOUT) continue;
        int b_ = m_ & 31, o_ = m_ >> 5;
#pragma unroll
        for (int j = 0; j < 8; j++) {
            int n_ = n0 + tn0 + j;
            if (n_ >= ODIM_) continue;
            Cout[(size_t)(b_ * OLEN + o_) * ODIM_ + n_] = acc[i][j] + bias[n_];
        }
    }
}

extern "C" void kernel_launch(void* const* d_in, const int* in_sizes, int n_in,
                              void* d_out, int out_size) {
    const float* hpad   = (const float*)d_in[0];
    const int*   ys     = (const int*)d_in[1];
    const float* w_enc  = (const float*)d_in[2];
    const float* b_enc  = (const float*)d_in[3];
    const float* w_dec  = (const float*)d_in[4];
    const float* w_att  = (const float*)d_in[5];
    const float* w_conv = (const float*)d_in[6];
    const float* w_gvec = (const float*)d_in[7];
    const float* embed  = (const float*)d_in[9];
    const float* w_ih   = (const float*)d_in[10];
    const float* w_hh   = (const float*)d_in[11];
    const float* b_ih   = (const float*)d_in[12];
    const float* b_hh   = (const float*)d_in[13];
    const float* w_out  = (const float*)d_in[14];
    const float* b_out  = (const float*)d_in[15];
    float* out = (float*)d_out;

    k_prep<<<8192, 256>>>(w_ih, w_hh, hpad, w_att);
    k_gemms<<<1832, 256>>>(hpad, w_enc, b_enc, w_ih, b_ih, b_hh, ys, embed);

    for (int step = 0; step < OLEN; step++) {
        k_small<<<384, 256>>>(w_dec, w_conv, step);
        k_e<<<dim3(50, BB), 128>>>(w_gvec);
        k_ctx<<<dim3(8, BB), 256>>>();
        k_lstm<<<256, 128>>>(step);
    }
    k_out<<<dim3(40, 26), 256>>>(w_out, b_out, out);
}

// round 15
// speedup vs baseline: 1.3471x; 1.1307x over previous
#include <cuda_runtime.h>
#include <cuda_fp16.h>
#include <mma.h>
using namespace nvcuda;

#define BB 32
#define TT 1000
#define EE 512
#define DD 1024
#define AA 512
#define CC 10
#define FF 100
#define KW 201
#define ODIM_ 5000
#define LL 100
#define OLEN 101
#define SOS_ 4998
#define NROW 4096
#define KCAT2 1536
#define MOUT 3232
#define MOUT_PAD 3328

__device__ __half g_preh[BB * TT * AA];          // 32.8 MB
__device__ __half g_hpadh[BB * TT * EE];         // 32.8 MB (also A of pre-GEMM)
__device__ __half g_wcat2h[NROW * KCAT2];        // 12.6 MB
__device__ float g_gey[MOUT_PAD * NROW];         // 54.5 MB (streamed)
__device__ __half g_w_ench[EE * EE];
__device__ __half g_w_ihh[NROW * DD];
__device__ __half g_w_outh[5120 * DD];           // rows >=5000 stay zero (zero-init)
__device__ __half g_eyh[MOUT_PAD * DD];
__device__ __half g_zallh[MOUT_PAD * DD];        // pad rows stay zero
__device__ float g_bias2[NROW];
__device__ __half2 g_wattp[10 * 256];
__device__ float g_aw[BB * TT];
__device__ float g_e[BB * TT];                   // exp(2e)
__device__ float g_epart[BB * 50];
__device__ float g_conv[BB * CC * TT];
__device__ float g_decp[4][BB * AA];
__device__ float g_ctxp2[2][BB * EE];
__device__ float g_z[2][BB * DD];
__device__ float g_c[BB * DD];

__device__ __forceinline__ __half2 tanh2(__half2 x) {
    unsigned xi = *reinterpret_cast<unsigned*>(&x), yi;
    asm("tanh.approx.f16x2 %0, %1;" : "=r"(yi) : "r"(xi));
    return *reinterpret_cast<__half2*>(&yi);
}

// ---------- pre-loop: init + all fp16 packs ----------
__global__ void k_prep(const float* __restrict__ w_ih, const float* __restrict__ w_hh,
                       const float* __restrict__ hpad, const float* __restrict__ w_att,
                       const float* __restrict__ w_enc, const float* __restrict__ w_out,
                       const float* __restrict__ embed, const int* __restrict__ ys,
                       const float* __restrict__ b_ih, const float* __restrict__ b_hh) {
    const size_t TOT = 35731200;
    for (size_t i = (size_t)blockIdx.x * 256 + threadIdx.x; i < TOT; i += 2097152) {
        if (i < 32768) {
            g_z[0][i] = 0.f; g_c[i] = 0.f;
        } else if (i < 64768) {
            g_aw[i - 32768] = 1.0f / TT;
        } else if (i < 6356224) {
            int j = (int)(i - 64768);
            int r = j / KCAT2, k = j - r * KCAT2;
            int n = (r & 3) * DD + (r >> 2);
            float v = (k < EE) ? w_ih[(size_t)n * (DD + EE) + DD + k]
                               : w_hh[(size_t)n * DD + (k - EE)];
            g_wcat2h[j] = __float2half(v);
        } else if (i < 22740224) {
            size_t j = i - 6356224;
            g_hpadh[j] = __float2half(hpad[j]);
        } else if (i < 22742784) {
            int j = (int)(i - 22740224);
            int c = j >> 8, p = j & 255;
            g_wattp[j] = __floats2half2_rn(w_att[(2 * p) * CC + c],
                                           w_att[(2 * p + 1) * CC + c]);
        } else if (i < 23004928) {
            int j = (int)(i - 22742784);
            g_w_ench[j] = __float2half(w_enc[j]);
        } else if (i < 27199232) {
            int j = (int)(i - 23004928);
            int r = j >> 10, k = j & (DD - 1);
            int n = (r & 3) * DD + (r >> 2);
            g_w_ihh[j] = __float2half(w_ih[(size_t)n * (DD + EE) + k]);
        } else if (i < 32319232) {
            int j = (int)(i - 27199232);
            g_w_outh[j] = __float2half(w_out[j]);
        } else if (i < 35727104) {
            int j = (int)(i - 32319232);
            int m = j >> 10, k = j & (DD - 1);
            int s = m >> 5, b = m & 31;
            int tok = (s == 0 || s > 100) ? SOS_ : ys[b * LL + s - 1];
            g_eyh[j] = __float2half(embed[(size_t)tok * DD + k]);
        } else {
            int r = (int)(i - 35727104);
            int n = (r & 3) * DD + (r >> 2);
            g_bias2[r] = b_ih[n] + b_hh[n];
        }
    }
}

// ---------- wmma GEMM: C[M][N] = A[M][K](fp16) * B[N][K](fp16)^T + bias ----------
// MODE 0: A=hpadh,B=w_ench -> preh fp16.  MODE 1: A=eyh,B=w_ihh -> gey fp32.
// MODE 2: A=zallh,B=w_outh -> scatter fp32 to out.
template <int MODE>
__global__ __launch_bounds__(256) void k_hgemm(const float* __restrict__ bias_p,
                                               float* __restrict__ Cout, int K) {
    __shared__ __align__(16) char smraw[34816];
    __half* Ah = (__half*)smraw;                  // [128][40]
    __half* Bh = (__half*)(smraw + 10240);        // [64][40]
    float* Cs = (float*)smraw;                    // [128][68] (reused after K loop)
    const __half* A = (MODE == 0) ? g_hpadh : (MODE == 1) ? g_eyh : g_zallh;
    const __half* Bm = (MODE == 0) ? g_w_ench : (MODE == 1) ? g_w_ihh : g_w_outh;
    int tid = threadIdx.x;
    int m0 = blockIdx.y * 128, n0 = blockIdx.x * 64;
    int wid = tid >> 5;
    int wm = wid >> 1, wn = wid & 1;

    wmma::fragment<wmma::accumulator, 16, 16, 16, float> cf[2][2];
#pragma unroll
    for (int i = 0; i < 2; i++)
#pragma unroll
        for (int j = 0; j < 2; j++) wmma::fill_fragment(cf[i][j], 0.f);

    for (int k0 = 0; k0 < K; k0 += 32) {
#pragma unroll
        for (int i = 0; i < 2; i++) {
            int lin = tid + (i << 8);
            int row = lin >> 2, c8 = (lin & 3) << 3;
            *(uint4*)&Ah[row * 40 + c8] =
                *(const uint4*)(A + (size_t)(m0 + row) * K + k0 + c8);
        }
        {
            int row = tid >> 2, c8 = (tid & 3) << 3;
            *(uint4*)&Bh[row * 40 + c8] =
                *(const uint4*)(Bm + (size_t)(n0 + row) * K + k0 + c8);
        }
        __syncthreads();
#pragma unroll
        for (int kk = 0; kk < 32; kk += 16) {
            wmma::fragment<wmma::matrix_a, 16, 16, 16, __half, wmma::row_major> af[2];
            wmma::fragment<wmma::matrix_b, 16, 16, 16, __half, wmma::col_major> bf[2];
#pragma unroll
            for (int i = 0; i < 2; i++)
                wmma::load_matrix_sync(af[i], &Ah[(wm * 32 + i * 16) * 40 + kk], 40);
#pragma unroll
            for (int j = 0; j < 2; j++)
                wmma::load_matrix_sync(bf[j], &Bh[(wn * 32 + j * 16) * 40 + kk], 40);
#pragma unroll
            for (int i = 0; i < 2; i++)
#pragma unroll
                for (int j = 0; j < 2; j++)
                    wmma::mma_sync(cf[i][j], af[i], bf[j], cf[i][j]);
        }
        __syncthreads();
    }
#pragma unroll
    for (int i = 0; i < 2; i++)
#pragma unroll
        for (int j = 0; j < 2; j++)
            wmma::store_matrix_sync(&Cs[(wm * 32 + i * 16) * 68 + wn * 32 + j * 16],
                                    cf[i][j], 68, wmma::mem_row_major);
    __syncthreads();
    for (int e = tid; e < 128 * 64; e += 256) {
        int r = e >> 6, c = e & 63;
        int m_ = m0 + r, n_ = n0 + c;
        float v = Cs[r * 68 + c];
        if (MODE == 0) {
            g_preh[(size_t)m_ * EE + n_] = __float2half(v + bias_p[n_]);
        } else if (MODE == 1) {
            __stcs(&g_gey[(size_t)m_ * NROW + n_], v + g_bias2[n_]);
        } else {
            if (m_ < MOUT && n_ < ODIM_) {
                int b_ = m_ & 31, o_ = m_ >> 5;
                Cout[(size_t)(b_ * OLEN + o_) * ODIM_ + n_] = v + bias_p[n_];
            }
        }
    }
}

// ---------- per-step: conv(aw) [0..319] + dec GEMM K-split [320..383] ----------
__global__ __launch_bounds__(256) void k_small(const float* __restrict__ w_dec,
                                               const float* __restrict__ w_conv, int step) {
    int blk = blockIdx.x, tid = threadIdx.x;
    if (blk < BB * CC) {
        __shared__ float sm[1408];
        int b = blk / CC, c = blk - b * CC;
        float* aw_s = sm;
        float* wk = sm + 1200;
        for (int i = tid; i < TT + 2 * FF; i += 256)
            aw_s[i] = (i >= FF && i < FF + TT) ? g_aw[b * TT + i - FF] : 0.f;
        for (int i = tid; i < KW; i += 256) wk[i] = w_conv[c * KW + i];
        __syncthreads();
        for (int t = tid; t < TT; t += 256) {
            float s = 0.f;
#pragma unroll 4
            for (int k = 0; k < KW; k++) s = fmaf(wk[k], aw_s[t + k], s);
            g_conv[(b * CC + c) * TT + t] = s;
        }
    } else {
        __shared__ float ws2[32][68];
        __shared__ float zs[64][36];
        int blk2 = blk - BB * CC;
        int ks = blk2 & 3, at = blk2 >> 2;
        int a0 = at * 32;
        int kbase = ks * 256;
        int zr = step & 1;
        int al = tid >> 3, bq = (tid & 7) << 2;
        int bbz = tid >> 3, kk0 = tid & 7;
        const float* zsrc = g_z[zr];
        float a0v = 0.f, a1v = 0.f, a2v = 0.f, a3v = 0.f;
        for (int kc = 0; kc < 4; kc++) {
            int k0 = kbase + kc * 64;
            __syncthreads();
#pragma unroll
            for (int i = 0; i < 2; i++) {
                int lin = tid + (i << 8);
                int row = lin >> 4, kq = (lin & 15) << 2;
                float4 w4 = *(const float4*)(w_dec + (size_t)(a0 + row) * DD + k0 + kq);
                ws2[row][kq + 0] = w4.x; ws2[row][kq + 1] = w4.y;
                ws2[row][kq + 2] = w4.z; ws2[row][kq + 3] = w4.w;
            }
#pragma unroll
            for (int j = 0; j < 8; j++) {
                int kk = kk0 + (j << 3);
                zs[kk][bbz] = zsrc[bbz * DD + k0 + kk];
            }
            __syncthreads();
#pragma unroll
            for (int kk = 0; kk < 64; kk++) {
                float w = ws2[al][kk];
                float4 x = *(const float4*)&zs[kk][bq];
                a0v = fmaf(w, x.x, a0v); a1v = fmaf(w, x.y, a1v);
                a2v = fmaf(w, x.z, a2v); a3v = fmaf(w, x.w, a3v);
            }
        }
        g_decp[ks][(bq + 0) * AA + a0 + al] = a0v;
        g_decp[ks][(bq + 1) * AA + a0 + al] = a1v;
        g_decp[ks][(bq + 2) * AA + a0 + al] = a2v;
        g_decp[ks][(bq + 3) * AA + a0 + al] = a3v;
    }
}

// ---------- per-step: exp(2*e[b,t]) half2 math, 10-deep load batches ----------
__global__ __launch_bounds__(128) void k_e(const float* __restrict__ w_gvec) {
    int b = blockIdx.y, t0 = blockIdx.x * 20;
    int tid = threadIdx.x;
    __shared__ __half2 conv_s2[20][10];
    __shared__ float part_s[20][4];
    __shared__ float exps[20];
    for (int i = tid; i < 200; i += 128) {
        int c = i / 20, tl = i - c * 20;
        conv_s2[tl][c] = __float2half2_rn(g_conv[(b * CC + c) * TT + t0 + tl]);
    }
    int a0 = tid * 4, p0 = tid * 2;
    __half2 wr2[2][10];
    float gg[4], dcf[4];
#pragma unroll
    for (int pp = 0; pp < 2; pp++)
#pragma unroll
        for (int c = 0; c < 10; c++) wr2[pp][c] = g_wattp[(c << 8) + p0 + pp];
#pragma unroll
    for (int j = 0; j < 4; j++) {
        gg[j] = w_gvec[a0 + j];
        int ai = b * AA + a0 + j;
        dcf[j] = g_decp[0][ai] + g_decp[1][ai] + g_decp[2][ai] + g_decp[3][ai];
    }
    __half2 dch0 = __floats2half2_rn(dcf[0], dcf[1]);
    __half2 dch1 = __floats2half2_rn(dcf[2], dcf[3]);
    __syncthreads();
    int lane = tid & 31, warp = tid >> 5;
    const __half2* prep = (const __half2*)(g_preh + ((size_t)b * TT + t0) * AA + a0);
    for (int tq = 0; tq < 20; tq += 10) {
        uint2 u[10];
#pragma unroll
        for (int q = 0; q < 10; q++)
            u[q] = *(const uint2*)(prep + (size_t)(tq + q) * (AA / 2));
        float acc[10];
#pragma unroll
        for (int q = 0; q < 10; q++) {
            __half2 pa0 = *reinterpret_cast<__half2*>(&u[q].x);
            __half2 pa1 = *reinterpret_cast<__half2*>(&u[q].y);
            __half2 x0 = __hadd2(pa0, dch0);
            __half2 x1 = __hadd2(pa1, dch1);
#pragma unroll
            for (int c = 0; c < 10; c++) {
                __half2 cvt = conv_s2[tq + q][c];
                x0 = __hfma2(cvt, wr2[0][c], x0);
                x1 = __hfma2(cvt, wr2[1][c], x1);
            }
            float2 f0 = __half22float2(tanh2(x0));
            float2 f1 = __half22float2(tanh2(x1));
            acc[q] = gg[0] * f0.x + gg[1] * f0.y + gg[2] * f1.x + gg[3] * f1.y;
        }
#pragma unroll
        for (int s = 16; s; s >>= 1) {
#pragma unroll
            for (int q = 0; q < 10; q++)
                acc[q] += __shfl_xor_sync(0xffffffffu, acc[q], s);
        }
        if (lane == 0) {
#pragma unroll
            for (int q = 0; q < 10; q++) part_s[tq + q][warp] = acc[q];
        }
    }
    __syncthreads();
    if (tid < 20) {
        float e = part_s[tid][0] + part_s[tid][1] + part_s[tid][2] + part_s[tid][3];
        float ex = __expf(2.f * e);
        g_e[b * TT + t0 + tid] = ex;
        exps[tid] = ex;
    }
    __syncthreads();
    if (tid == 0) {
        float s = 0.f;
#pragma unroll
        for (int i = 0; i < 20; i++) s += exps[i];
        g_epart[b * 50 + blockIdx.x] = s;
    }
}

// ---------- per-step: normalize + ctx partials (25-deep half2 ldcs batches) + aw ----------
__global__ __launch_bounds__(256) void k_ctx() {
    int b = blockIdx.y;
    int ec = blockIdx.x & 3, tc = blockIdx.x >> 2;
    int tid = threadIdx.x;
    __shared__ float wsm[500];
    __shared__ float sred[64];
    __shared__ float2 red2[256];
    if (tid < 64) sred[tid] = (tid < 50) ? g_epart[b * 50 + tid] : 0.f;
    __syncthreads();
    if (tid < 32) {
        float v = sred[tid] + sred[tid + 32];
#pragma unroll
        for (int s = 16; s; s >>= 1) v += __shfl_xor_sync(0xffffffffu, v, s);
        if (tid == 0) sred[0] = v;
    }
    __syncthreads();
    float inv = 1.f / sred[0];
    int tbase = tc * 500;
    for (int i = tid; i < 500; i += 256) {
        float w = g_e[b * TT + tbase + i] * inv;
        wsm[i] = w;
        if (ec == 0) g_aw[b * TT + tbase + i] = w;
    }
    __syncthreads();
    int el2 = (tid & 63) * 2, h = tid >> 6;
    int e0 = ec * 128;
    const __half2* hp =
        (const __half2*)(g_hpadh + ((size_t)b * TT + tbase + h * 125) * EE + e0 + el2);
    const float* wp = wsm + h * 125;
    float ax = 0.f, ay = 0.f;
    for (int i0 = 0; i0 < 125; i0 += 25) {
        __half2 hv[25];
#pragma unroll
        for (int q = 0; q < 25; q++)
            hv[q] = __ldcs(hp + (size_t)(i0 + q) * 256);
#pragma unroll
        for (int q = 0; q < 25; q++) {
            float2 f = __half22float2(hv[q]);
            float w = wp[i0 + q];
            ax = fmaf(w, f.x, ax); ay = fmaf(w, f.y, ay);
        }
    }
    red2[tid] = make_float2(ax, ay);
    __syncthreads();
    if (tid < 64) {
        float2 s0 = red2[tid], s1 = red2[tid + 64];
        float2 s2 = red2[tid + 128], s3 = red2[tid + 192];
        g_ctxp2[tc][b * EE + e0 + tid * 2 + 0] = s0.x + s1.x + s2.x + s3.x;
        g_ctxp2[tc][b * EE + e0 + tid * 2 + 1] = s0.y + s1.y + s2.y + s3.y;
    }
}

// ---------- per-step: LSTM gates, double-buffered smem pipeline + cell ----------
__global__ __launch_bounds__(128) void k_lstm(int step) {
    __shared__ float ws[2][16][68];
    __shared__ float xs[2][64][36];
    __shared__ float gates_s[16][33];
    int tid = threadIdx.x;
    int r0 = blockIdx.x * 16;
    int zr = step & 1;
    int rl = tid >> 3, b0 = (tid & 7) << 2;
    int bb = tid >> 2, kk0 = tid & 3;
    float acc0 = __ldcs(&g_gey[(size_t)(step * BB + b0 + 0) * NROW + r0 + rl]);
    float acc1 = __ldcs(&g_gey[(size_t)(step * BB + b0 + 1) * NROW + r0 + rl]);
    float acc2 = __ldcs(&g_gey[(size_t)(step * BB + b0 + 2) * NROW + r0 + rl]);
    float acc3 = __ldcs(&g_gey[(size_t)(step * BB + b0 + 3) * NROW + r0 + rl]);
    const float* zsrc = g_z[zr];
    int wrow = tid >> 3, wkq = (tid & 7) << 3;

    uint4 w8;
    float xv[16];
    w8 = *(const uint4*)(g_wcat2h + (size_t)(r0 + wrow) * KCAT2 + wkq);
#pragma unroll
    for (int j = 0; j < 16; j++) {
        int k = kk0 + (j << 2);
        xv[j] = (k < EE) ? (g_ctxp2[0][bb * EE + k] + g_ctxp2[1][bb * EE + k])
                         : zsrc[bb * DD + (k - EE)];
    }
    for (int c = 0; c < 24; c++) {
        int p = c & 1;
        {
            __half2* hp = (__half2*)&w8;
            float2 f0 = __half22float2(hp[0]);
            float2 f1 = __half22float2(hp[1]);
            float2 f2 = __half22float2(hp[2]);
            float2 f3 = __half22float2(hp[3]);
            ws[p][wrow][wkq + 0] = f0.x; ws[p][wrow][wkq + 1] = f0.y;
            ws[p][wrow][wkq + 2] = f1.x; ws[p][wrow][wkq + 3] = f1.y;
            ws[p][wrow][wkq + 4] = f2.x; ws[p][wrow][wkq + 5] = f2.y;
            ws[p][wrow][wkq + 6] = f3.x; ws[p][wrow][wkq + 7] = f3.y;
        }
#pragma unroll
        for (int j = 0; j < 16; j++) xs[p][kk0 + (j << 2)][bb] = xv[j];
        __syncthreads();
        if (c < 23) {
            int k0 = (c + 1) * 64;
            w8 = *(const uint4*)(g_wcat2h + (size_t)(r0 + wrow) * KCAT2 + k0 + wkq);
#pragma unroll
            for (int j = 0; j < 16; j++) {
                int k = k0 + kk0 + (j << 2);
                xv[j] = (k < EE) ? (g_ctxp2[0][bb * EE + k] + g_ctxp2[1][bb * EE + k])
                                 : zsrc[bb * DD + (k - EE)];
            }
        }
#pragma unroll
        for (int kk = 0; kk < 64; kk++) {
            float w = ws[p][rl][kk];
            float4 x = *(const float4*)&xs[p][kk][b0];
            acc0 = fmaf(w, x.x, acc0); acc1 = fmaf(w, x.y, acc1);
            acc2 = fmaf(w, x.z, acc2); acc3 = fmaf(w, x.w, acc3);
        }
    }
    __syncthreads();
    gates_s[rl][b0 + 0] = acc0;
    gates_s[rl][b0 + 1] = acc1;
    gates_s[rl][b0 + 2] = acc2;
    gates_s[rl][b0 + 3] = acc3;
    __syncthreads();
    int dl = tid >> 5, b = tid & 31;
    int d = (r0 >> 2) + dl;
    float iv = gates_s[dl * 4 + 0][b];
    float fv = gates_s[dl * 4 + 1][b];
    float gv = gates_s[dl * 4 + 2][b];
    float ov = gates_s[dl * 4 + 3][b];
    float si = 1.f / (1.f + expf(-iv));
    float sf = 1.f / (1.f + expf(-fv));
    float so = 1.f / (1.f + expf(-ov));
    float cn = sf * g_c[b * DD + d] + si * tanhf(gv);
    float zn = so * tanhf(cn);
    g_c[b * DD + d] = cn;
    g_z[zr ^ 1][b * DD + d] = zn;
    g_zallh[(size_t)(step * BB + b) * DD + d] = __float2half(zn);
}

extern "C" void kernel_launch(void* const* d_in, const int* in_sizes, int n_in,
                              void* d_out, int out_size) {
    const float* hpad   = (const float*)d_in[0];
    const int*   ys     = (const int*)d_in[1];
    const float* w_enc  = (const float*)d_in[2];
    const float* b_enc  = (const float*)d_in[3];
    const float* w_dec  = (const float*)d_in[4];
    const float* w_att  = (const float*)d_in[5];
    const float* w_conv = (const float*)d_in[6];
    const float* w_gvec = (const float*)d_in[7];
    const float* embed  = (const float*)d_in[9];
    const float* w_ih   = (const float*)d_in[10];
    const float* w_hh   = (const float*)d_in[11];
    const float* b_ih   = (const float*)d_in[12];
    const float* b_hh   = (const float*)d_in[13];
    const float* w_out  = (const float*)d_in[14];
    const float* b_out  = (const float*)d_in[15];
    float* out = (float*)d_out;

    k_prep<<<8192, 256>>>(w_ih, w_hh, hpad, w_att, w_enc, w_out, embed, ys, b_ih, b_hh);
    k_hgemm<0><<<dim3(8, 250), 256>>>(b_enc, nullptr, 512);     // pre
    k_hgemm<1><<<dim3(64, 26), 256>>>(nullptr, nullptr, 1024);  // gey

    for (int step = 0; step < OLEN; step++) {
        k_small<<<384, 256>>>(w_dec, w_conv, step);
        k_e<<<dim3(50, BB), 128>>>(w_gvec);
        k_ctx<<<dim3(8, BB), 256>>>();
        k_lstm<<<256, 128>>>(step);
    }
    k_hgemm<2><<<dim3(80, 26), 256>>>(b_out, out, 1024);        // out
}